// round 1
// baseline (speedup 1.0000x reference)
#include <cuda_runtime.h>
#include <math.h>

#define NN 50000
#define NE 400000
#define D_IN 32
#define D_H 128
#define D_EF 8
#define N_L 2
#define D_OUT 16
#define PC 640            // packed per-node projection columns: 4*128 + 2*64
#define NT ((NN + 63) / 64)
#define LN_EPS 1e-5f

// ------------------------- scratch (device globals) -------------------------
__device__ float g_x[NN * D_H];            // current node features
__device__ float g_aggr[NN * D_H];         // scatter-add accumulator
__device__ float g_P[NN * PC];             // per-node projections (current layer)
__device__ float g_Wpack[N_L][D_H * PC];   // packed projection weights
__device__ float g_Wf[N_L][2][D_EF * D_H]; // folded edge_attr weights (l, type)
__device__ float g_bf[N_L][2][D_H];        // folded bias (b_edge@W1e + b1)
__device__ int   g_perm[NE];
__device__ int   g_cnt[2];
__device__ float g_pool[D_H];

// ------------------------- k_zero: counters, pool, static outputs -----------
__global__ void k_zero(float* out, const float* beam, const float* ris) {
    int t = threadIdx.x;
    if (t < 2) g_cnt[t] = 0;
    if (t < D_H) g_pool[t] = 0.f;
    if (t < 64) out[t] = beam[t];
    else if (t < 164) out[t] = ris[t - 64];
}

// ------------------------- k_partition: split edges by type ------------------
__global__ void k_partition(const int* __restrict__ edge_type) {
    int e = blockIdx.x * blockDim.x + threadIdx.x;
    if (e >= NE) return;
    int et = edge_type[e];
    int pos = et ? (NE - 1 - atomicAdd(&g_cnt[1], 1)) : atomicAdd(&g_cnt[0], 1);
    g_perm[pos] = e;
}

// ------------------------- k_fold: fold W_edge into W1[256:384] --------------
__global__ void k_fold(const float* __restrict__ W_leg1, const float* __restrict__ b_leg1,
                       const float* __restrict__ W_eav1, const float* __restrict__ b_eav1,
                       const float* __restrict__ W_edge, const float* __restrict__ b_edge) {
    __shared__ float sW[64 * D_H];
    __shared__ float sWe[D_EF * D_H];
    __shared__ float sbe[D_H];
    int l = blockIdx.x >> 1, t = blockIdx.x & 1;
    const float* W1 = (t ? W_eav1 : W_leg1) + l * 384 * D_H;
    const float* b1 = (t ? b_eav1 : b_leg1) + l * D_H;
    int tid = threadIdx.x; // 128 threads
    for (int idx = tid; idx < D_EF * D_H; idx += 128) sWe[idx] = W_edge[idx];
    sbe[tid] = b_edge[tid];
    float accb = b1[tid];
    float accj[D_EF];
#pragma unroll
    for (int j = 0; j < D_EF; j++) accj[j] = 0.f;
    for (int cb = 0; cb < 2; cb++) {
        __syncthreads();
        for (int idx = tid; idx < 64 * D_H; idx += 128)
            sW[idx] = W1[(256 + cb * 64 + (idx >> 7)) * D_H + (idx & 127)];
        __syncthreads();
        for (int c2 = 0; c2 < 64; c2++) {
            float w = sW[c2 * D_H + tid];
            int c = cb * 64 + c2;
            accb = fmaf(sbe[c], w, accb);
#pragma unroll
            for (int j = 0; j < D_EF; j++) accj[j] = fmaf(sWe[j * D_H + c], w, accj[j]);
        }
    }
    g_bf[l][t][tid] = accb;
#pragma unroll
    for (int j = 0; j < D_EF; j++) g_Wf[l][t][j * D_H + tid] = accj[j];
}

// ------------------------- k_pack: pack projection weights -------------------
// cols 0:128 leg(dst), 128:256 leg(src), 256:384 eav(dst), 384:512 eav(src),
// 512:576 att(dst, 64), 576:640 att(src, 64)
__global__ void k_pack(const float* __restrict__ W_leg1, const float* __restrict__ W_eav1,
                       const float* __restrict__ W_att1) {
    int l = blockIdx.x / 5, ch = blockIdx.x % 5;
    for (int idx = threadIdx.x; idx < 128 * 128; idx += blockDim.x) {
        int c = idx >> 7, k = idx & 127;
        float v;
        if (ch < 4) {
            const float* W1 = ((ch >> 1) ? W_eav1 : W_leg1) + l * 384 * D_H;
            v = W1[((ch & 1) * 128 + c) * D_H + k];
        } else {
            const float* Wa = W_att1 + l * 256 * 64;
            v = (k < 64) ? Wa[c * 64 + k] : Wa[(128 + c) * 64 + (k - 64)];
        }
        g_Wpack[l][c * PC + ch * 128 + k] = v;
    }
}

// ------------------------- k_embed: x = x_in @ W_node + b --------------------
__global__ void __launch_bounds__(256) k_embed(const float* __restrict__ x_in,
                                               const float* __restrict__ W_node,
                                               const float* __restrict__ b_node) {
    __shared__ float sA[64][D_IN + 1];
    __shared__ __align__(16) float sB[D_IN * D_H];
    __shared__ float sb[D_H];
    int tid = threadIdx.x;
    int row0 = blockIdx.x * 64;
    for (int idx = tid; idx < 64 * D_IN; idx += 256) {
        int i = idx >> 5, c = idx & 31;
        int r = row0 + i;
        sA[i][c] = (r < NN) ? x_in[r * D_IN + c] : 0.f;
    }
    for (int idx = tid; idx < D_IN * D_H; idx += 256) sB[idx] = W_node[idx];
    if (tid < D_H) sb[tid] = b_node[tid];
    __syncthreads();
    int tx = tid & 15, ty = tid >> 4;
    float acc[4][8];
#pragma unroll
    for (int r = 0; r < 4; r++)
#pragma unroll
        for (int j = 0; j < 8; j++) acc[r][j] = 0.f;
    for (int c = 0; c < D_IN; c++) {
        float a[4];
#pragma unroll
        for (int r = 0; r < 4; r++) a[r] = sA[ty * 4 + r][c];
        float4 b0 = *(const float4*)(sB + c * D_H + tx * 8);
        float4 b1 = *(const float4*)(sB + c * D_H + tx * 8 + 4);
        float bb[8] = {b0.x, b0.y, b0.z, b0.w, b1.x, b1.y, b1.z, b1.w};
#pragma unroll
        for (int r = 0; r < 4; r++)
#pragma unroll
            for (int j = 0; j < 8; j++) acc[r][j] = fmaf(a[r], bb[j], acc[r][j]);
    }
#pragma unroll
    for (int r = 0; r < 4; r++) {
        int row = row0 + ty * 4 + r;
        if (row < NN) {
#pragma unroll
            for (int j = 0; j < 8; j++) {
                int col = tx * 8 + j;
                g_x[row * D_H + col] = acc[r][j] + sb[col];
            }
        }
    }
}

// ------------------------- k_proj: P = x @ Wpack[l] --------------------------
__global__ void __launch_bounds__(256) k_proj(int l) {
    extern __shared__ __align__(16) float sm[];
    float* sA = sm;               // 64 x 129
    float* sB = sm + 64 * 129;    // 128 x 128
    int tid = threadIdx.x;
    int row0 = blockIdx.x * 64;
    int ch = blockIdx.y;
    for (int idx = tid; idx < 64 * D_H; idx += 256) {
        int i = idx >> 7, k = idx & 127;
        int r = row0 + i;
        sA[i * 129 + k] = (r < NN) ? g_x[r * D_H + k] : 0.f;
    }
    const float* Wp = g_Wpack[l];
    for (int idx = tid; idx < 128 * 128; idx += 256) {
        int c = idx >> 7, k = idx & 127;
        sB[idx] = Wp[c * PC + ch * 128 + k];
    }
    __syncthreads();
    int tx = tid & 15, ty = tid >> 4;
    float acc[4][8];
#pragma unroll
    for (int r = 0; r < 4; r++)
#pragma unroll
        for (int j = 0; j < 8; j++) acc[r][j] = 0.f;
    for (int c = 0; c < D_H; c++) {
        float a[4];
#pragma unroll
        for (int r = 0; r < 4; r++) a[r] = sA[(ty * 4 + r) * 129 + c];
        float4 b0 = *(const float4*)(sB + c * D_H + tx * 8);
        float4 b1 = *(const float4*)(sB + c * D_H + tx * 8 + 4);
        float bb[8] = {b0.x, b0.y, b0.z, b0.w, b1.x, b1.y, b1.z, b1.w};
#pragma unroll
        for (int r = 0; r < 4; r++)
#pragma unroll
            for (int j = 0; j < 8; j++) acc[r][j] = fmaf(a[r], bb[j], acc[r][j]);
    }
#pragma unroll
    for (int r = 0; r < 4; r++) {
        int row = row0 + ty * 4 + r;
        if (row < NN) {
#pragma unroll
            for (int j = 0; j < 8; j++)
                g_P[row * PC + ch * 128 + tx * 8 + j] = acc[r][j];
        }
    }
}

// ------------------------- k_edge: fused edge MLP + gate + scatter -----------
__global__ void __launch_bounds__(256) k_edge(
    int l, const int* __restrict__ edge_index, const int* __restrict__ edge_type,
    const float* __restrict__ edge_attr,
    const float* __restrict__ W_leg2, const float* __restrict__ b_leg2,
    const float* __restrict__ W_eav2, const float* __restrict__ b_eav2,
    const float* __restrict__ W_att2, const float* __restrict__ b_att2,
    const float* __restrict__ b_att1) {
    extern __shared__ __align__(16) char smraw[];
    int* s_dst = (int*)smraw;
    int* s_src = s_dst + 64;
    int* s_et  = s_src + 64;
    float* fb    = (float*)(smraw + 1024);
    float* s_ea  = fb;            // 64*8
    float* s_Wf  = s_ea + 512;    // 8*128
    float* s_bf  = s_Wf + 1024;   // 128
    float* s_ba1 = s_bf + 128;    // 64
    float* s_wa2 = s_ba1 + 64;    // 64
    float* s_att = s_wa2 + 64;    // 64
    float* s_hid = s_att + 64;    // 64*129
    float* s_B   = s_hid + 64 * 129; // 128*128 (overlaid with s_atth 64*65)
    float* s_atth = s_B;
    __shared__ int sh_np, sh_t0;

    int tid = threadIdx.x;
    int tile0 = blockIdx.x * 64;
    if (tid < 64) {
        int e = g_perm[tile0 + tid];
        s_src[tid] = edge_index[e];
        s_dst[tid] = edge_index[NE + e];
        s_et[tid]  = edge_type[e];
#pragma unroll
        for (int j = 0; j < D_EF; j++) s_ea[tid * D_EF + j] = edge_attr[e * D_EF + j];
    } else if (tid < 128) {
        s_ba1[tid - 64] = b_att1[l * 64 + (tid - 64)];
    } else if (tid < 192) {
        s_wa2[tid - 128] = W_att2[l * 64 + (tid - 128)];
    }
    __syncthreads();
    if (tid == 0) {
        int t0 = s_et[0];
        int uni = 1;
        for (int i = 1; i < 64; i++) if (s_et[i] != t0) { uni = 0; break; }
        sh_t0 = t0;
        sh_np = uni ? 1 : 2;
    }
    __syncthreads();
    int npasses = sh_np;
    float ba2 = b_att2[l];

    for (int p = 0; p < npasses; p++) {
        int t = (npasses == 1) ? sh_t0 : p;
        // stage folded edge weights
        for (int idx = tid; idx < D_EF * D_H; idx += 256) s_Wf[idx] = g_Wf[l][t][idx];
        if (tid < D_H) s_bf[tid] = g_bf[l][t][tid];
        __syncthreads();
        // phase1: hidden = relu(P_dst + P_src + edge_attr@Wf + bf)
        {
            int k = tid & 127, ih = tid >> 7;
            int cD = t ? 256 : 0;
            for (int i = ih; i < 64; i += 2) {
                int d = s_dst[i], s = s_src[i];
                float acc = s_bf[k] + g_P[d * PC + cD + k] + g_P[s * PC + cD + 128 + k];
#pragma unroll
                for (int j = 0; j < D_EF; j++)
                    acc = fmaf(s_ea[i * D_EF + j], s_Wf[j * D_H + k], acc);
                s_hid[i * 129 + k] = fmaxf(acc, 0.f);
            }
        }
        __syncthreads();
        // attention gate (only for type-1 pass)
        if (t == 1) {
            for (int idx = tid; idx < 64 * 64; idx += 256) {
                int i = idx >> 6, m = idx & 63;
                int d = s_dst[i], s = s_src[i];
                float v = g_P[d * PC + 512 + m] + g_P[s * PC + 576 + m] + s_ba1[m];
                s_atth[i * 65 + m] = fmaxf(v, 0.f);
            }
            __syncthreads();
            if (tid < 64) {
                float z = 0.f;
                for (int m = 0; m < 64; m++) z += s_atth[tid * 65 + m] * s_wa2[m];
                z += ba2;
                s_att[tid] = 1.f / (1.f + expf(-z));
            }
            __syncthreads();
        }
        // load W2
        const float* W2 = (t ? W_eav2 : W_leg2) + l * D_H * D_H;
        const float* b2 = (t ? b_eav2 : b_leg2) + l * D_H;
        for (int idx = tid * 4; idx < D_H * D_H; idx += 1024)
            *(float4*)(s_B + idx) = *(const float4*)(W2 + idx);
        __syncthreads();
        // GEMM2: out = hidden @ W2
        int tx = tid & 15, ty = tid >> 4;
        float acc[4][8];
#pragma unroll
        for (int r = 0; r < 4; r++)
#pragma unroll
            for (int j = 0; j < 8; j++) acc[r][j] = 0.f;
        for (int c = 0; c < D_H; c++) {
            float a[4];
#pragma unroll
            for (int r = 0; r < 4; r++) a[r] = s_hid[(ty * 4 + r) * 129 + c];
            float4 b0v = *(const float4*)(s_B + c * D_H + tx * 8);
            float4 b1v = *(const float4*)(s_B + c * D_H + tx * 8 + 4);
            float bb[8] = {b0v.x, b0v.y, b0v.z, b0v.w, b1v.x, b1v.y, b1v.z, b1v.w};
#pragma unroll
            for (int r = 0; r < 4; r++)
#pragma unroll
                for (int j = 0; j < 8; j++) acc[r][j] = fmaf(a[r], bb[j], acc[r][j]);
        }
        float bias[8];
#pragma unroll
        for (int j = 0; j < 8; j++) bias[j] = b2[tx * 8 + j];
        // writeback: scatter-add gated message
#pragma unroll
        for (int r = 0; r < 4; r++) {
            int i = ty * 4 + r;
            if (npasses == 1 || s_et[i] == t) {
                float sc = t ? s_att[i] : 1.f;
                float* dp = g_aggr + s_dst[i] * D_H + tx * 8;
#pragma unroll
                for (int j = 0; j < 8; j++)
                    atomicAdd(dp + j, (acc[r][j] + bias[j]) * sc);
            }
        }
        __syncthreads();
    }
}

// ------------------------- k_update: upd MLP + LN + residual -----------------
__global__ void __launch_bounds__(256) k_update(
    int l, const float* __restrict__ W_upd, const float* __restrict__ b_upd,
    const float* __restrict__ ln_g, const float* __restrict__ ln_b) {
    extern __shared__ __align__(16) float sm[];
    float* sA  = sm;                   // 64 x 260 ([x | aggr] padded)
    float* sB  = sA + 64 * 260;        // 64 x 128 (K chunk)
    float* sH  = sB + 64 * 128;        // 64 x 129
    float* sMu = sH + 64 * 129;        // 64
    float* sRs = sMu + 64;             // 64
    int tid = threadIdx.x;
    int row0 = blockIdx.x * 64;
    for (int idx = tid; idx < 64 * 256; idx += 256) {
        int i = idx >> 8, c = idx & 255;
        int r = row0 + i;
        float v = 0.f;
        if (r < NN) v = (c < 128) ? g_x[r * D_H + c] : g_aggr[r * D_H + (c - 128)];
        sA[i * 260 + c] = v;
    }
    __syncthreads();
    int tx = tid & 15, ty = tid >> 4;
    float acc[4][8];
#pragma unroll
    for (int r = 0; r < 4; r++)
#pragma unroll
        for (int j = 0; j < 8; j++) acc[r][j] = 0.f;
    const float* W = W_upd + l * 256 * D_H;
    for (int kk = 0; kk < 4; kk++) {
        for (int idx = tid; idx < 64 * 128; idx += 256) {
            int c = idx >> 7, k = idx & 127;
            sB[idx] = W[(kk * 64 + c) * D_H + k];
        }
        __syncthreads();
        for (int c = 0; c < 64; c++) {
            float a[4];
#pragma unroll
            for (int r = 0; r < 4; r++) a[r] = sA[(ty * 4 + r) * 260 + kk * 64 + c];
            float4 b0v = *(const float4*)(sB + c * D_H + tx * 8);
            float4 b1v = *(const float4*)(sB + c * D_H + tx * 8 + 4);
            float bb[8] = {b0v.x, b0v.y, b0v.z, b0v.w, b1v.x, b1v.y, b1v.z, b1v.w};
#pragma unroll
            for (int r = 0; r < 4; r++)
#pragma unroll
                for (int j = 0; j < 8; j++) acc[r][j] = fmaf(a[r], bb[j], acc[r][j]);
        }
        __syncthreads();
    }
#pragma unroll
    for (int r = 0; r < 4; r++) {
#pragma unroll
        for (int j = 0; j < 8; j++) {
            int col = tx * 8 + j;
            sH[(ty * 4 + r) * 129 + col] = acc[r][j] + b_upd[l * D_H + col];
        }
    }
    __syncthreads();
    if (tid < 64) {
        float m = 0.f;
        for (int k = 0; k < D_H; k++) m += sH[tid * 129 + k];
        m *= (1.f / D_H);
        float v = 0.f;
        for (int k = 0; k < D_H; k++) {
            float d = sH[tid * 129 + k] - m;
            v += d * d;
        }
        v *= (1.f / D_H);
        sMu[tid] = m;
        sRs[tid] = rsqrtf(v + LN_EPS);
    }
    __syncthreads();
    {
        int k = tid & 127, ih = tid >> 7;
        float g = ln_g[l * D_H + k], b = ln_b[l * D_H + k];
        for (int i = ih; i < 64; i += 2) {
            int r = row0 + i;
            if (r < NN) {
                float h = (sH[i * 129 + k] - sMu[i]) * sRs[i] * g + b;
                float v = fmaxf(h, 0.f) + sA[i * 260 + k]; // + x_old
                g_x[r * D_H + k] = fmaxf(v, 0.f);
            }
        }
    }
}

// ------------------------- k_pool: sum x over nodes --------------------------
__global__ void k_pool() {
    __shared__ float sp[256];
    int tid = threadIdx.x;
    int row0 = blockIdx.x * 64;
    int k = tid & 127, ih = tid >> 7;
    float v = 0.f;
    for (int i = ih; i < 64; i += 2) {
        int r = row0 + i;
        if (r < NN) v += g_x[r * D_H + k];
    }
    sp[tid] = v;
    __syncthreads();
    if (tid < 128) atomicAdd(&g_pool[k], sp[tid] + sp[tid + 128]);
}

// ------------------------- k_head: refinement head + output ------------------
__global__ void k_head(float* out, const float* __restrict__ traj,
                       const float* __restrict__ W_ref1, const float* __restrict__ b_ref1,
                       const float* __restrict__ W_ref2, const float* __restrict__ b_ref2) {
    __shared__ float sg[D_H], sr1[D_H];
    int tid = threadIdx.x; // 128
    sg[tid] = g_pool[tid] * (1.f / NN);
    __syncthreads();
    float acc = b_ref1[tid];
    for (int c = 0; c < D_H; c++) acc = fmaf(sg[c], W_ref1[c * D_H + tid], acc);
    sr1[tid] = fmaxf(acc, 0.f);
    __syncthreads();
    if (tid < D_OUT) {
        float r2 = b_ref2[tid];
        for (int c = 0; c < D_H; c++) r2 = fmaf(sr1[c], W_ref2[c * D_OUT + tid], r2);
        if (tid < 3) out[164 + tid] = traj[tid] + r2;
    }
    out[167 + tid] = sg[tid];
}

// ------------------------- launch ------------------------------------------
extern "C" void kernel_launch(void* const* d_in, const int* in_sizes, int n_in,
                              void* d_out, int out_size) {
    const float* x_in      = (const float*)d_in[0];
    const float* edge_attr = (const float*)d_in[1];
    const int*   edge_index= (const int*)d_in[2];
    const int*   edge_type = (const int*)d_in[3];
    // d_in[4] = batch (all zeros, unused)
    const float* beam      = (const float*)d_in[5];
    const float* ris       = (const float*)d_in[6];
    const float* traj      = (const float*)d_in[7];
    const float* W_node = (const float*)d_in[8];
    const float* b_node = (const float*)d_in[9];
    const float* W_edge = (const float*)d_in[10];
    const float* b_edge = (const float*)d_in[11];
    const float* W_leg1 = (const float*)d_in[12];
    const float* b_leg1 = (const float*)d_in[13];
    const float* W_leg2 = (const float*)d_in[14];
    const float* b_leg2 = (const float*)d_in[15];
    const float* W_eav1 = (const float*)d_in[16];
    const float* b_eav1 = (const float*)d_in[17];
    const float* W_eav2 = (const float*)d_in[18];
    const float* b_eav2 = (const float*)d_in[19];
    const float* W_att1 = (const float*)d_in[20];
    const float* b_att1 = (const float*)d_in[21];
    const float* W_att2 = (const float*)d_in[22];
    const float* b_att2 = (const float*)d_in[23];
    const float* W_upd  = (const float*)d_in[24];
    const float* b_upd  = (const float*)d_in[25];
    const float* ln_g   = (const float*)d_in[26];
    const float* ln_b   = (const float*)d_in[27];
    const float* W_ref1 = (const float*)d_in[28];
    const float* b_ref1 = (const float*)d_in[29];
    const float* W_ref2 = (const float*)d_in[30];
    const float* b_ref2 = (const float*)d_in[31];
    float* out = (float*)d_out;

    const int SMEM_PROJ = (64 * 129 + 128 * 128) * 4;
    const int SMEM_EDGE = 1024 + (512 + 1024 + 128 + 64 + 64 + 64 + 64 * 129 + 128 * 128) * 4;
    const int SMEM_UPD  = (64 * 260 + 64 * 128 + 64 * 129 + 128) * 4;
    cudaFuncSetAttribute(k_proj,   cudaFuncAttributeMaxDynamicSharedMemorySize, SMEM_PROJ);
    cudaFuncSetAttribute(k_edge,   cudaFuncAttributeMaxDynamicSharedMemorySize, SMEM_EDGE);
    cudaFuncSetAttribute(k_update, cudaFuncAttributeMaxDynamicSharedMemorySize, SMEM_UPD);

    void* aggr_ptr = nullptr;
    cudaGetSymbolAddress(&aggr_ptr, g_aggr);

    k_zero<<<1, 256>>>(out, beam, ris);
    k_partition<<<(NE + 255) / 256, 256>>>(edge_type);
    k_fold<<<4, 128>>>(W_leg1, b_leg1, W_eav1, b_eav1, W_edge, b_edge);
    k_pack<<<10, 256>>>(W_leg1, W_eav1, W_att1);
    k_embed<<<NT, 256>>>(x_in, W_node, b_node);

    for (int l = 0; l < N_L; l++) {
        cudaMemsetAsync(aggr_ptr, 0, (size_t)NN * D_H * sizeof(float));
        k_proj<<<dim3(NT, 5), 256, SMEM_PROJ>>>(l);
        k_edge<<<NE / 64, 256, SMEM_EDGE>>>(l, edge_index, edge_type, edge_attr,
                                            W_leg2, b_leg2, W_eav2, b_eav2,
                                            W_att2, b_att2, b_att1);
        k_update<<<NT, 256, SMEM_UPD>>>(l, W_upd, b_upd, ln_g, ln_b);
    }

    k_pool<<<NT, 256>>>();
    k_head<<<1, 128>>>(out, traj, W_ref1, b_ref1, W_ref2, b_ref2);
}

// round 2
// speedup vs baseline: 1.1722x; 1.1722x over previous
#include <cuda_runtime.h>
#include <math.h>

#define NN 50000
#define NE 400000
#define D_IN 32
#define D_H 128
#define D_EF 8
#define N_L 2
#define D_OUT 16
#define PC 640            // packed per-node projection columns: 4*128 + 2*64
#define NT64 ((NN + 63) / 64)
#define NT128 ((NN + 127) / 128)
#define LN_EPS 1e-5f

typedef unsigned long long u64;

// ------------------------- scratch (device globals) -------------------------
__device__ float g_x[NN * D_H];            // current node features
__device__ float g_aggr[NN * D_H];         // scatter-add accumulator
__device__ float g_P[NN * PC];             // per-node projections (current layer)
__device__ float g_Wpack[N_L][D_H * PC];   // packed projection weights
__device__ float g_Wf[N_L][2][D_EF * D_H]; // folded edge_attr weights (l, type)
__device__ float g_bf[N_L][2][D_H];        // folded bias (b_edge@W1e + b1)
__device__ int   g_perm[NE];
__device__ int   g_cnt[2];
__device__ float g_pool[D_H];

// ------------------------- packed-fma micro-GEMM helpers --------------------
__device__ __forceinline__ u64 pack2(float a) {
    u64 r;
    unsigned int au = __float_as_uint(a);
    asm("mov.b64 %0, {%1, %1};" : "=l"(r) : "r"(au));
    return r;
}
__device__ __forceinline__ void fma2(u64& d, u64 a, u64 b) {
    asm("fma.rn.f32x2 %0, %1, %2, %0;" : "+l"(d) : "l"(a), "l"(b));
}
__device__ __forceinline__ void unpack2(u64 v, float& lo, float& hi) {
    asm("mov.b64 {%0, %1}, %2;" : "=f"(lo), "=f"(hi) : "l"(v));
}
// accumulate C[128x128] += A[128 x K] * B[K x 128]; A row stride lda, B row stride 128
__device__ __forceinline__ void mmtile(const float* sA, int lda, const float* sB, int K,
                                       int ty, int tx, u64 acc[8][4]) {
    for (int c = 0; c < K; c++) {
        u64 a2[8];
#pragma unroll
        for (int r = 0; r < 8; r++) a2[r] = pack2(sA[(ty * 8 + r) * lda + c]);
        ulonglong2 b01 = *(const ulonglong2*)(sB + c * 128 + tx * 8);
        ulonglong2 b23 = *(const ulonglong2*)(sB + c * 128 + tx * 8 + 4);
        u64 bb[4] = {b01.x, b01.y, b23.x, b23.y};
#pragma unroll
        for (int r = 0; r < 8; r++)
#pragma unroll
            for (int j = 0; j < 4; j++) fma2(acc[r][j], a2[r], bb[j]);
    }
}

__device__ __forceinline__ void red4(float* p, float4 v) {
    asm volatile("red.global.add.v4.f32 [%0], {%1,%2,%3,%4};"
                 :: "l"(p), "f"(v.x), "f"(v.y), "f"(v.z), "f"(v.w) : "memory");
}

// ------------------------- k_zero -------------------------------------------
__global__ void k_zero(float* out, const float* beam, const float* ris) {
    int t = threadIdx.x;
    if (t < 2) g_cnt[t] = 0;
    if (t < D_H) g_pool[t] = 0.f;
    if (t < 64) out[t] = beam[t];
    else if (t < 164) out[t] = ris[t - 64];
}

// ------------------------- k_partition ---------------------------------------
__global__ void k_partition(const int* __restrict__ edge_type) {
    int e = blockIdx.x * blockDim.x + threadIdx.x;
    if (e >= NE) return;
    int et = edge_type[e];
    int pos = et ? (NE - 1 - atomicAdd(&g_cnt[1], 1)) : atomicAdd(&g_cnt[0], 1);
    g_perm[pos] = e;
}

// ------------------------- k_fold --------------------------------------------
__global__ void k_fold(const float* __restrict__ W_leg1, const float* __restrict__ b_leg1,
                       const float* __restrict__ W_eav1, const float* __restrict__ b_eav1,
                       const float* __restrict__ W_edge, const float* __restrict__ b_edge) {
    __shared__ float sW[64 * D_H];
    __shared__ float sWe[D_EF * D_H];
    __shared__ float sbe[D_H];
    int l = blockIdx.x >> 1, t = blockIdx.x & 1;
    const float* W1 = (t ? W_eav1 : W_leg1) + l * 384 * D_H;
    const float* b1 = (t ? b_eav1 : b_leg1) + l * D_H;
    int tid = threadIdx.x; // 128 threads
    for (int idx = tid; idx < D_EF * D_H; idx += 128) sWe[idx] = W_edge[idx];
    sbe[tid] = b_edge[tid];
    float accb = b1[tid];
    float accj[D_EF];
#pragma unroll
    for (int j = 0; j < D_EF; j++) accj[j] = 0.f;
    for (int cb = 0; cb < 2; cb++) {
        __syncthreads();
        for (int idx = tid; idx < 64 * D_H; idx += 128)
            sW[idx] = W1[(256 + cb * 64 + (idx >> 7)) * D_H + (idx & 127)];
        __syncthreads();
        for (int c2 = 0; c2 < 64; c2++) {
            float w = sW[c2 * D_H + tid];
            int c = cb * 64 + c2;
            accb = fmaf(sbe[c], w, accb);
#pragma unroll
            for (int j = 0; j < D_EF; j++) accj[j] = fmaf(sWe[j * D_H + c], w, accj[j]);
        }
    }
    g_bf[l][t][tid] = accb;
#pragma unroll
    for (int j = 0; j < D_EF; j++) g_Wf[l][t][j * D_H + tid] = accj[j];
}

// ------------------------- k_pack --------------------------------------------
__global__ void k_pack(const float* __restrict__ W_leg1, const float* __restrict__ W_eav1,
                       const float* __restrict__ W_att1) {
    int l = blockIdx.x / 5, ch = blockIdx.x % 5;
    for (int idx = threadIdx.x; idx < 128 * 128; idx += blockDim.x) {
        int c = idx >> 7, k = idx & 127;
        float v;
        if (ch < 4) {
            const float* W1 = ((ch >> 1) ? W_eav1 : W_leg1) + l * 384 * D_H;
            v = W1[((ch & 1) * 128 + c) * D_H + k];
        } else {
            const float* Wa = W_att1 + l * 256 * 64;
            v = (k < 64) ? Wa[c * 64 + k] : Wa[(128 + c) * 64 + (k - 64)];
        }
        g_Wpack[l][c * PC + ch * 128 + k] = v;
    }
}

// ------------------------- k_embed: x = x_in @ W_node + b --------------------
__global__ void __launch_bounds__(256) k_embed(const float* __restrict__ x_in,
                                               const float* __restrict__ W_node,
                                               const float* __restrict__ b_node) {
    __shared__ float sA[64][D_IN + 1];
    __shared__ __align__(16) float sB[D_IN * D_H];
    __shared__ float sb[D_H];
    int tid = threadIdx.x;
    int row0 = blockIdx.x * 64;
    for (int idx = tid; idx < 64 * D_IN; idx += 256) {
        int i = idx >> 5, c = idx & 31;
        int r = row0 + i;
        sA[i][c] = (r < NN) ? x_in[r * D_IN + c] : 0.f;
    }
    for (int idx = tid; idx < D_IN * D_H; idx += 256) sB[idx] = W_node[idx];
    if (tid < D_H) sb[tid] = b_node[tid];
    __syncthreads();
    int tx = tid & 15, ty = tid >> 4;
    float acc[4][8];
#pragma unroll
    for (int r = 0; r < 4; r++)
#pragma unroll
        for (int j = 0; j < 8; j++) acc[r][j] = 0.f;
    for (int c = 0; c < D_IN; c++) {
        float a[4];
#pragma unroll
        for (int r = 0; r < 4; r++) a[r] = sA[ty * 4 + r][c];
        float4 b0 = *(const float4*)(sB + c * D_H + tx * 8);
        float4 b1 = *(const float4*)(sB + c * D_H + tx * 8 + 4);
        float bb[8] = {b0.x, b0.y, b0.z, b0.w, b1.x, b1.y, b1.z, b1.w};
#pragma unroll
        for (int r = 0; r < 4; r++)
#pragma unroll
            for (int j = 0; j < 8; j++) acc[r][j] = fmaf(a[r], bb[j], acc[r][j]);
    }
#pragma unroll
    for (int r = 0; r < 4; r++) {
        int row = row0 + ty * 4 + r;
        if (row < NN) {
#pragma unroll
            for (int j = 0; j < 8; j++) {
                int col = tx * 8 + j;
                g_x[row * D_H + col] = acc[r][j] + sb[col];
            }
        }
    }
}

// ------------------------- k_proj: P = x @ Wpack[l] (128x128 packed tiles) ---
__global__ void __launch_bounds__(256, 1) k_proj(int l) {
    extern __shared__ __align__(16) float sm[];
    float* sA = sm;               // 128 x 128
    float* sB = sm + 128 * 128;   // 128 x 128
    int tid = threadIdx.x;
    int row0 = blockIdx.x * 128;
    int ch = blockIdx.y;
    const float* Wp = g_Wpack[l];
    for (int idx = tid; idx < 128 * 32; idx += 256) {
        int i = idx >> 5, k4 = (idx & 31) * 4;
        int r = row0 + i;
        float4 v = make_float4(0.f, 0.f, 0.f, 0.f);
        if (r < NN) v = *(const float4*)(g_x + r * D_H + k4);
        *(float4*)(sA + i * 128 + k4) = v;
    }
    for (int idx = tid; idx < 128 * 32; idx += 256) {
        int c = idx >> 5, k4 = (idx & 31) * 4;
        *(float4*)(sB + c * 128 + k4) = *(const float4*)(Wp + c * PC + ch * 128 + k4);
    }
    __syncthreads();
    int tx = tid & 15, ty = tid >> 4;
    u64 acc[8][4];
#pragma unroll
    for (int r = 0; r < 8; r++)
#pragma unroll
        for (int j = 0; j < 4; j++) acc[r][j] = 0ull;
    mmtile(sA, 128, sB, 128, ty, tx, acc);
#pragma unroll
    for (int r = 0; r < 8; r++) {
        int row = row0 + ty * 8 + r;
        if (row < NN) {
            float o[8];
#pragma unroll
            for (int j = 0; j < 4; j++) unpack2(acc[r][j], o[2 * j], o[2 * j + 1]);
            float* dp = g_P + row * PC + ch * 128 + tx * 8;
            *(float4*)dp = make_float4(o[0], o[1], o[2], o[3]);
            *(float4*)(dp + 4) = make_float4(o[4], o[5], o[6], o[7]);
        }
    }
}

// ------------------------- k_edge: fused edge MLP + gate + scatter -----------
// 128-edge tiles, packed-fma GEMM2, vectorized red scatter.
__global__ void __launch_bounds__(256, 1) k_edge(
    int l, const int* __restrict__ edge_index, const int* __restrict__ edge_type,
    const float* __restrict__ edge_attr,
    const float* __restrict__ W_leg2, const float* __restrict__ b_leg2,
    const float* __restrict__ W_eav2, const float* __restrict__ b_eav2,
    const float* __restrict__ W_att2, const float* __restrict__ b_att2,
    const float* __restrict__ b_att1) {
    extern __shared__ __align__(16) char smraw[];
    int* s_dst = (int*)smraw;                 // 128
    int* s_src = s_dst + 128;                 // 128
    int* s_et  = s_src + 128;                 // 128
    float* s_ea  = (float*)(smraw + 1536);    // 128*8   -> +4096 = 5632
    float* s_Wf  = (float*)(smraw + 5632);    // 8*128   -> +4096 = 9728
    float* s_bf  = (float*)(smraw + 9728);    // 128     -> +512  = 10240
    float* s_ba1 = (float*)(smraw + 10240);   // 64      -> +256  = 10496
    float* s_wa2 = (float*)(smraw + 10496);   // 64      -> +256  = 10752
    float* s_att = (float*)(smraw + 10752);   // 128     -> +512  = 11264
    float* s_hid = (float*)(smraw + 11264);   // 128*128 -> +65536 = 76800
    float* s_B   = (float*)(smraw + 76800);   // 128*128 -> +65536 = 142336
    float* s_atth = s_B;                      // 128*65 overlay (used before B load)
    __shared__ int sh_np, sh_t0;

    int tid = threadIdx.x;
    int tile0 = blockIdx.x * 128;
    if (tid < 128) {
        int e = g_perm[tile0 + tid];
        s_src[tid] = edge_index[e];
        s_dst[tid] = edge_index[NE + e];
        s_et[tid]  = edge_type[e];
#pragma unroll
        for (int j = 0; j < D_EF; j++) s_ea[tid * D_EF + j] = edge_attr[e * D_EF + j];
    } else if (tid < 192) {
        s_ba1[tid - 128] = b_att1[l * 64 + (tid - 128)];
    } else {
        s_wa2[tid - 192] = W_att2[l * 64 + (tid - 192)];
    }
    __syncthreads();
    if (tid == 0) {
        int t0 = s_et[0];
        sh_t0 = t0;
        sh_np = (s_et[127] == t0) ? 1 : 2;   // partition => within-tile types contiguous
    }
    __syncthreads();
    int npasses = sh_np;
    float ba2 = b_att2[l];
    int tx = tid & 15, ty = tid >> 4;

    for (int p = 0; p < npasses; p++) {
        int t = (npasses == 1) ? sh_t0 : p;
        // stage folded edge weights
        for (int idx = tid; idx < D_EF * D_H; idx += 256) s_Wf[idx] = g_Wf[l][t][idx];
        if (tid < D_H) s_bf[tid] = g_bf[l][t][tid];
        __syncthreads();
        // phase1: hidden = relu(P_dst + P_src + edge_attr@Wf + bf)
        {
            int k = tid & 127, ih = tid >> 7;
            int cD = t ? 256 : 0;
#pragma unroll 4
            for (int i = ih; i < 128; i += 2) {
                int d = s_dst[i], s = s_src[i];
                float acc = s_bf[k] + __ldg(g_P + d * PC + cD + k) +
                            __ldg(g_P + s * PC + cD + 128 + k);
#pragma unroll
                for (int j = 0; j < D_EF; j++)
                    acc = fmaf(s_ea[i * D_EF + j], s_Wf[j * D_H + k], acc);
                s_hid[i * 128 + k] = fmaxf(acc, 0.f);
            }
        }
        __syncthreads();
        // attention gate (type-1 pass only)
        if (t == 1) {
            for (int idx = tid; idx < 128 * 64; idx += 256) {
                int i = idx >> 6, m = idx & 63;
                int d = s_dst[i], s = s_src[i];
                float v = __ldg(g_P + d * PC + 512 + m) + __ldg(g_P + s * PC + 576 + m) + s_ba1[m];
                s_atth[i * 65 + m] = fmaxf(v, 0.f);
            }
            __syncthreads();
            if (tid < 128) {
                float z = ba2;
                for (int m = 0; m < 64; m++) z = fmaf(s_atth[tid * 65 + m], s_wa2[m], z);
                s_att[tid] = 1.f / (1.f + expf(-z));
            }
            __syncthreads();
        }
        // stage W2 (overwrites s_atth region)
        const float* W2 = (t ? W_eav2 : W_leg2) + l * D_H * D_H;
        const float* b2 = (t ? b_eav2 : b_leg2) + l * D_H;
        for (int idx = tid * 4; idx < D_H * D_H; idx += 1024)
            *(float4*)(s_B + idx) = *(const float4*)(W2 + idx);
        __syncthreads();
        // GEMM2: msg = hidden @ W2 (packed fma)
        u64 acc[8][4];
#pragma unroll
        for (int r = 0; r < 8; r++)
#pragma unroll
            for (int j = 0; j < 4; j++) acc[r][j] = 0ull;
        mmtile(s_hid, 128, s_B, 128, ty, tx, acc);
        float bias[8];
#pragma unroll
        for (int j = 0; j < 8; j++) bias[j] = b2[tx * 8 + j];
        // scatter-add gated message (vector red)
#pragma unroll
        for (int r = 0; r < 8; r++) {
            int i = ty * 8 + r;
            if (npasses == 1 || s_et[i] == t) {
                float sc = t ? s_att[i] : 1.f;
                float o[8];
#pragma unroll
                for (int j = 0; j < 4; j++) unpack2(acc[r][j], o[2 * j], o[2 * j + 1]);
                float* dp = g_aggr + s_dst[i] * D_H + tx * 8;
                red4(dp, make_float4((o[0] + bias[0]) * sc, (o[1] + bias[1]) * sc,
                                     (o[2] + bias[2]) * sc, (o[3] + bias[3]) * sc));
                red4(dp + 4, make_float4((o[4] + bias[4]) * sc, (o[5] + bias[5]) * sc,
                                         (o[6] + bias[6]) * sc, (o[7] + bias[7]) * sc));
            }
        }
        __syncthreads();
    }
}

// ------------------------- k_update: upd MLP + LN + residual (128-row tiles) -
__global__ void __launch_bounds__(256, 1) k_update(
    int l, const float* __restrict__ W_upd, const float* __restrict__ b_upd,
    const float* __restrict__ ln_g, const float* __restrict__ ln_b) {
    extern __shared__ __align__(16) float sm[];
    float* sA  = sm;                   // 128 x 64 (K chunk of [x|aggr])
    float* sB  = sA + 128 * 64;        // 64 x 128
    float* sH  = sB + 64 * 128;        // 128 x 129 (padded for LN)
    float* sMu = sH + 128 * 129;       // 128
    float* sRs = sMu + 128;            // 128
    int tid = threadIdx.x;
    int row0 = blockIdx.x * 128;
    int tx = tid & 15, ty = tid >> 4;
    u64 acc[8][4];
#pragma unroll
    for (int r = 0; r < 8; r++)
#pragma unroll
        for (int j = 0; j < 4; j++) acc[r][j] = 0ull;
    const float* W = W_upd + l * 256 * D_H;
    for (int kk = 0; kk < 4; kk++) {
        const float* Asrc = (kk < 2) ? g_x : g_aggr;
        int cbase = (kk & 1) * 64;
        for (int idx = tid; idx < 128 * 16; idx += 256) {
            int i = idx >> 4, c4 = (idx & 15) * 4;
            int r = row0 + i;
            float4 v = make_float4(0.f, 0.f, 0.f, 0.f);
            if (r < NN) v = *(const float4*)(Asrc + r * D_H + cbase + c4);
            *(float4*)(sA + i * 64 + c4) = v;
        }
        for (int idx = tid; idx < 64 * 32; idx += 256) {
            int c = idx >> 5, k4 = (idx & 31) * 4;
            *(float4*)(sB + c * 128 + k4) = *(const float4*)(W + (kk * 64 + c) * D_H + k4);
        }
        __syncthreads();
        mmtile(sA, 64, sB, 64, ty, tx, acc);
        __syncthreads();
    }
    // write h + bias into padded sH
#pragma unroll
    for (int r = 0; r < 8; r++) {
        float o[8];
#pragma unroll
        for (int j = 0; j < 4; j++) unpack2(acc[r][j], o[2 * j], o[2 * j + 1]);
#pragma unroll
        for (int j = 0; j < 8; j++) {
            int col = tx * 8 + j;
            sH[(ty * 8 + r) * 129 + col] = o[j] + b_upd[l * D_H + col];
        }
    }
    __syncthreads();
    if (tid < 128) {
        float m = 0.f;
        for (int k = 0; k < D_H; k++) m += sH[tid * 129 + k];
        m *= (1.f / D_H);
        float v = 0.f;
        for (int k = 0; k < D_H; k++) {
            float d = sH[tid * 129 + k] - m;
            v = fmaf(d, d, v);
        }
        v *= (1.f / D_H);
        sMu[tid] = m;
        sRs[tid] = rsqrtf(v + LN_EPS);
    }
    __syncthreads();
    {
        int k = tid & 127, ih = tid >> 7;
        float g = ln_g[l * D_H + k], b = ln_b[l * D_H + k];
        for (int i = ih; i < 128; i += 2) {
            int r = row0 + i;
            if (r < NN) {
                float h = (sH[i * 129 + k] - sMu[i]) * sRs[i] * g + b;
                float v = fmaxf(h, 0.f) + g_x[r * D_H + k]; // + x_old (residual)
                g_x[r * D_H + k] = fmaxf(v, 0.f);
            }
        }
    }
}

// ------------------------- k_pool -------------------------------------------
__global__ void k_pool() {
    __shared__ float sp[256];
    int tid = threadIdx.x;
    int row0 = blockIdx.x * 64;
    int k = tid & 127, ih = tid >> 7;
    float v = 0.f;
    for (int i = ih; i < 64; i += 2) {
        int r = row0 + i;
        if (r < NN) v += g_x[r * D_H + k];
    }
    sp[tid] = v;
    __syncthreads();
    if (tid < 128) atomicAdd(&g_pool[k], sp[tid] + sp[tid + 128]);
}

// ------------------------- k_head -------------------------------------------
__global__ void k_head(float* out, const float* __restrict__ traj,
                       const float* __restrict__ W_ref1, const float* __restrict__ b_ref1,
                       const float* __restrict__ W_ref2, const float* __restrict__ b_ref2) {
    __shared__ float sg[D_H], sr1[D_H];
    int tid = threadIdx.x; // 128
    sg[tid] = g_pool[tid] * (1.f / NN);
    __syncthreads();
    float acc = b_ref1[tid];
    for (int c = 0; c < D_H; c++) acc = fmaf(sg[c], W_ref1[c * D_H + tid], acc);
    sr1[tid] = fmaxf(acc, 0.f);
    __syncthreads();
    if (tid < D_OUT) {
        float r2 = b_ref2[tid];
        for (int c = 0; c < D_H; c++) r2 = fmaf(sr1[c], W_ref2[c * D_OUT + tid], r2);
        if (tid < 3) out[164 + tid] = traj[tid] + r2;
    }
    out[167 + tid] = sg[tid];
}

// ------------------------- launch ------------------------------------------
extern "C" void kernel_launch(void* const* d_in, const int* in_sizes, int n_in,
                              void* d_out, int out_size) {
    const float* x_in      = (const float*)d_in[0];
    const float* edge_attr = (const float*)d_in[1];
    const int*   edge_index= (const int*)d_in[2];
    const int*   edge_type = (const int*)d_in[3];
    const float* beam      = (const float*)d_in[5];
    const float* ris       = (const float*)d_in[6];
    const float* traj      = (const float*)d_in[7];
    const float* W_node = (const float*)d_in[8];
    const float* b_node = (const float*)d_in[9];
    const float* W_edge = (const float*)d_in[10];
    const float* b_edge = (const float*)d_in[11];
    const float* W_leg1 = (const float*)d_in[12];
    const float* b_leg1 = (const float*)d_in[13];
    const float* W_leg2 = (const float*)d_in[14];
    const float* b_leg2 = (const float*)d_in[15];
    const float* W_eav1 = (const float*)d_in[16];
    const float* b_eav1 = (const float*)d_in[17];
    const float* W_eav2 = (const float*)d_in[18];
    const float* b_eav2 = (const float*)d_in[19];
    const float* W_att1 = (const float*)d_in[20];
    const float* b_att1 = (const float*)d_in[21];
    const float* W_att2 = (const float*)d_in[22];
    const float* b_att2 = (const float*)d_in[23];
    const float* W_upd  = (const float*)d_in[24];
    const float* b_upd  = (const float*)d_in[25];
    const float* ln_g   = (const float*)d_in[26];
    const float* ln_b   = (const float*)d_in[27];
    const float* W_ref1 = (const float*)d_in[28];
    const float* b_ref1 = (const float*)d_in[29];
    const float* W_ref2 = (const float*)d_in[30];
    const float* b_ref2 = (const float*)d_in[31];
    float* out = (float*)d_out;

    const int SMEM_PROJ = 2 * 128 * 128 * 4;                       // 131072
    const int SMEM_EDGE = 142336;
    const int SMEM_UPD  = (128 * 64 + 64 * 128 + 128 * 129 + 256) * 4; // 132608
    cudaFuncSetAttribute(k_proj,   cudaFuncAttributeMaxDynamicSharedMemorySize, SMEM_PROJ);
    cudaFuncSetAttribute(k_edge,   cudaFuncAttributeMaxDynamicSharedMemorySize, SMEM_EDGE);
    cudaFuncSetAttribute(k_update, cudaFuncAttributeMaxDynamicSharedMemorySize, SMEM_UPD);

    void* aggr_ptr = nullptr;
    cudaGetSymbolAddress(&aggr_ptr, g_aggr);

    k_zero<<<1, 256>>>(out, beam, ris);
    k_partition<<<(NE + 255) / 256, 256>>>(edge_type);
    k_fold<<<4, 128>>>(W_leg1, b_leg1, W_eav1, b_eav1, W_edge, b_edge);
    k_pack<<<10, 256>>>(W_leg1, W_eav1, W_att1);
    k_embed<<<NT64, 256>>>(x_in, W_node, b_node);

    for (int l = 0; l < N_L; l++) {
        cudaMemsetAsync(aggr_ptr, 0, (size_t)NN * D_H * sizeof(float));
        k_proj<<<dim3(NT128, 5), 256, SMEM_PROJ>>>(l);
        k_edge<<<NE / 128, 256, SMEM_EDGE>>>(l, edge_index, edge_type, edge_attr,
                                             W_leg2, b_leg2, W_eav2, b_eav2,
                                             W_att2, b_att2, b_att1);
        k_update<<<NT128, 256, SMEM_UPD>>>(l, W_upd, b_upd, ln_g, ln_b);
    }

    k_pool<<<NT64, 256>>>();
    k_head<<<1, 128>>>(out, traj, W_ref1, b_ref1, W_ref2, b_ref2);
}

// round 3
// speedup vs baseline: 2.0862x; 1.7798x over previous
#include <cuda_runtime.h>
#include <math.h>

#define NN 50000
#define NE 400000
#define D_IN 32
#define D_H 128
#define D_EF 8
#define N_L 2
#define D_OUT 16
#define PC 640            // packed per-node projection columns: 4*128 + 2*64
#define NT64 ((NN + 63) / 64)
#define NT128 ((NN + 127) / 128)
#define LN_EPS 1e-5f

typedef unsigned long long u64;

// ------------------------- scratch (device globals) -------------------------
__device__ float g_x[NN * D_H];
__device__ float g_aggr[NN * D_H];
__device__ float g_P[NN * PC];
__device__ float g_Wpack[N_L][D_H * PC];
__device__ float g_Wf[N_L][2][D_EF * D_H];
__device__ float g_bf[N_L][2][D_H];
__device__ int   g_perm[NE];
__device__ int   g_cnt[2];
__device__ float g_pool[D_H];

// ------------------------- packed-fma micro-GEMM helpers --------------------
__device__ __forceinline__ u64 pack2(float a) {
    u64 r;
    unsigned int au = __float_as_uint(a);
    asm("mov.b64 %0, {%1, %1};" : "=l"(r) : "r"(au));
    return r;
}
__device__ __forceinline__ void fma2(u64& d, u64 a, u64 b) {
    asm("fma.rn.f32x2 %0, %1, %2, %0;" : "+l"(d) : "l"(a), "l"(b));
}
__device__ __forceinline__ void unpack2(u64 v, float& lo, float& hi) {
    asm("mov.b64 {%0, %1}, %2;" : "=f"(lo), "=f"(hi) : "l"(v));
}
// C[128x128] += A[128 x K] * B[K x 128]; A row stride lda (odd => bank-safe)
__device__ __forceinline__ void mmtile(const float* sA, int lda, const float* sB, int K,
                                       int ty, int tx, u64 acc[8][4]) {
    for (int c = 0; c < K; c++) {
        u64 a2[8];
#pragma unroll
        for (int r = 0; r < 8; r++) a2[r] = pack2(sA[(ty * 8 + r) * lda + c]);
        ulonglong2 b01 = *(const ulonglong2*)(sB + c * 128 + tx * 8);
        ulonglong2 b23 = *(const ulonglong2*)(sB + c * 128 + tx * 8 + 4);
        u64 bb[4] = {b01.x, b01.y, b23.x, b23.y};
#pragma unroll
        for (int r = 0; r < 8; r++)
#pragma unroll
            for (int j = 0; j < 4; j++) fma2(acc[r][j], a2[r], bb[j]);
    }
}

__device__ __forceinline__ void red4(float* p, float4 v) {
    asm volatile("red.global.add.v4.f32 [%0], {%1,%2,%3,%4};"
                 :: "l"(p), "f"(v.x), "f"(v.y), "f"(v.z), "f"(v.w) : "memory");
}

// ------------------------- k_setup: fused zero + fold + pack -----------------
// block 0: zero/copy statics; blocks 1..4: fold; blocks 5..14: pack
__global__ void __launch_bounds__(256) k_setup(
    float* out, const float* beam, const float* ris,
    const float* __restrict__ W_leg1, const float* __restrict__ b_leg1,
    const float* __restrict__ W_eav1, const float* __restrict__ b_eav1,
    const float* __restrict__ W_edge, const float* __restrict__ b_edge,
    const float* __restrict__ W_att1) {
    int b = blockIdx.x, tid = threadIdx.x;
    if (b == 0) {
        if (tid < 2) g_cnt[tid] = 0;
        if (tid < D_H) g_pool[tid] = 0.f;
        if (tid < 64) out[tid] = beam[tid];
        else if (tid < 164) out[tid] = ris[tid - 64];
        return;
    }
    if (b <= 4) {
        __shared__ float sW[64 * D_H];
        __shared__ float sWe[D_EF * D_H];
        __shared__ float sbe[D_H];
        int l = (b - 1) >> 1, t = (b - 1) & 1;
        const float* W1 = (t ? W_eav1 : W_leg1) + l * 384 * D_H;
        const float* b1 = (t ? b_eav1 : b_leg1) + l * D_H;
        for (int idx = tid; idx < D_EF * D_H; idx += 256) sWe[idx] = W_edge[idx];
        if (tid < D_H) sbe[tid] = b_edge[tid];
        float accb = (tid < D_H) ? b1[tid] : 0.f;
        float accj[D_EF];
#pragma unroll
        for (int j = 0; j < D_EF; j++) accj[j] = 0.f;
        for (int cb = 0; cb < 2; cb++) {
            __syncthreads();
            for (int idx = tid; idx < 64 * D_H; idx += 256)
                sW[idx] = W1[(256 + cb * 64 + (idx >> 7)) * D_H + (idx & 127)];
            __syncthreads();
            if (tid < D_H) {
                for (int c2 = 0; c2 < 64; c2++) {
                    float w = sW[c2 * D_H + tid];
                    int c = cb * 64 + c2;
                    accb = fmaf(sbe[c], w, accb);
#pragma unroll
                    for (int j = 0; j < D_EF; j++) accj[j] = fmaf(sWe[j * D_H + c], w, accj[j]);
                }
            }
        }
        if (tid < D_H) {
            g_bf[l][t][tid] = accb;
#pragma unroll
            for (int j = 0; j < D_EF; j++) g_Wf[l][t][j * D_H + tid] = accj[j];
        }
        return;
    }
    // pack
    int l = (b - 5) / 5, ch = (b - 5) % 5;
    for (int idx = tid; idx < 128 * 128; idx += 256) {
        int c = idx >> 7, k = idx & 127;
        float v;
        if (ch < 4) {
            const float* W1 = ((ch >> 1) ? W_eav1 : W_leg1) + l * 384 * D_H;
            v = W1[((ch & 1) * 128 + c) * D_H + k];
        } else {
            const float* Wa = W_att1 + l * 256 * 64;
            v = (k < 64) ? Wa[c * 64 + k] : Wa[(128 + c) * 64 + (k - 64)];
        }
        g_Wpack[l][c * PC + ch * 128 + k] = v;
    }
}

// ------------------------- k_partition ---------------------------------------
__global__ void k_partition(const int* __restrict__ edge_type) {
    int e = blockIdx.x * blockDim.x + threadIdx.x;
    if (e >= NE) return;
    int et = edge_type[e];
    int pos = et ? (NE - 1 - atomicAdd(&g_cnt[1], 1)) : atomicAdd(&g_cnt[0], 1);
    g_perm[pos] = e;
}

// ------------------------- k_embed: x = x_in @ W_node + b --------------------
__global__ void __launch_bounds__(256) k_embed(const float* __restrict__ x_in,
                                               const float* __restrict__ W_node,
                                               const float* __restrict__ b_node) {
    __shared__ float sA[64][D_IN + 1];
    __shared__ __align__(16) float sB[D_IN * D_H];
    __shared__ float sb[D_H];
    int tid = threadIdx.x;
    int row0 = blockIdx.x * 64;
    for (int idx = tid; idx < 64 * D_IN; idx += 256) {
        int i = idx >> 5, c = idx & 31;
        int r = row0 + i;
        sA[i][c] = (r < NN) ? x_in[r * D_IN + c] : 0.f;
    }
    for (int idx = tid; idx < D_IN * D_H; idx += 256) sB[idx] = W_node[idx];
    if (tid < D_H) sb[tid] = b_node[tid];
    __syncthreads();
    int tx = tid & 15, ty = tid >> 4;
    float acc[4][8];
#pragma unroll
    for (int r = 0; r < 4; r++)
#pragma unroll
        for (int j = 0; j < 8; j++) acc[r][j] = 0.f;
    for (int c = 0; c < D_IN; c++) {
        float a[4];
#pragma unroll
        for (int r = 0; r < 4; r++) a[r] = sA[ty * 4 + r][c];
        float4 b0 = *(const float4*)(sB + c * D_H + tx * 8);
        float4 b1 = *(const float4*)(sB + c * D_H + tx * 8 + 4);
        float bb[8] = {b0.x, b0.y, b0.z, b0.w, b1.x, b1.y, b1.z, b1.w};
#pragma unroll
        for (int r = 0; r < 4; r++)
#pragma unroll
            for (int j = 0; j < 8; j++) acc[r][j] = fmaf(a[r], bb[j], acc[r][j]);
    }
#pragma unroll
    for (int r = 0; r < 4; r++) {
        int row = row0 + ty * 4 + r;
        if (row < NN) {
#pragma unroll
            for (int j = 0; j < 8; j++) {
                int col = tx * 8 + j;
                g_x[row * D_H + col] = acc[r][j] + sb[col];
            }
        }
    }
}

// ------------------------- k_proj: P = x @ Wpack[l] --------------------------
// sA 128x129 (padded), sB 64x128 K-chunks => 98.8KB smem, 2 blocks/SM
__global__ void __launch_bounds__(256, 2) k_proj(int l) {
    extern __shared__ __align__(16) float sm[];
    float* sA = sm;               // 128 x 129
    float* sB = sm + 128 * 129;   // 64 x 128
    int tid = threadIdx.x;
    int row0 = blockIdx.x * 128;
    int ch = blockIdx.y;
    const float* Wp = g_Wpack[l];
    for (int idx = tid; idx < 128 * 128; idx += 256) {
        int i = idx >> 7, k = idx & 127;
        int r = row0 + i;
        sA[i * 129 + k] = (r < NN) ? g_x[r * D_H + k] : 0.f;
    }
    int tx = tid & 15, ty = tid >> 4;
    u64 acc[8][4];
#pragma unroll
    for (int r = 0; r < 8; r++)
#pragma unroll
        for (int j = 0; j < 4; j++) acc[r][j] = 0ull;
    for (int kk = 0; kk < 2; kk++) {
        __syncthreads();
        for (int idx = tid; idx < 64 * 32; idx += 256) {
            int c = idx >> 5, k4 = (idx & 31) * 4;
            *(float4*)(sB + c * 128 + k4) = *(const float4*)(Wp + (kk * 64 + c) * PC + ch * 128 + k4);
        }
        __syncthreads();
        mmtile(sA + kk * 64, 129, sB, 64, ty, tx, acc);
    }
#pragma unroll
    for (int r = 0; r < 8; r++) {
        int row = row0 + ty * 8 + r;
        if (row < NN) {
            float o[8];
#pragma unroll
            for (int j = 0; j < 4; j++) unpack2(acc[r][j], o[2 * j], o[2 * j + 1]);
            float* dp = g_P + row * PC + ch * 128 + tx * 8;
            *(float4*)dp = make_float4(o[0], o[1], o[2], o[3]);
            *(float4*)(dp + 4) = make_float4(o[4], o[5], o[6], o[7]);
        }
    }
}

// ------------------------- k_edge --------------------------------------------
// 128-edge tiles; gate scratch lives in s_hid before phase1; W2 staged in
// 64-row K-chunks; ~110KB smem => 2 blocks/SM.
__global__ void __launch_bounds__(256, 2) k_edge(
    int l, const int* __restrict__ edge_index, const int* __restrict__ edge_type,
    const float* __restrict__ edge_attr,
    const float* __restrict__ W_leg2, const float* __restrict__ b_leg2,
    const float* __restrict__ W_eav2, const float* __restrict__ b_eav2,
    const float* __restrict__ W_att2, const float* __restrict__ b_att2,
    const float* __restrict__ b_att1) {
    extern __shared__ __align__(16) char smraw[];
    int* s_dst = (int*)smraw;                 // 128 (512B)
    int* s_src = (int*)(smraw + 512);         // 128
    int* s_et  = (int*)(smraw + 1024);        // 128
    float* s_ea  = (float*)(smraw + 1536);    // 128*8
    float* s_Wf  = (float*)(smraw + 5632);    // 8*128
    float* s_bf  = (float*)(smraw + 9728);    // 128
    float* s_ba1 = (float*)(smraw + 10240);   // 64
    float* s_wa2 = (float*)(smraw + 10496);   // 64
    float* s_att = (float*)(smraw + 10752);   // 128
    float* s_hid = (float*)(smraw + 11264);   // 128*129 = 66048B
    float* s_B   = (float*)(smraw + 77312);   // 64*128  = 32768B -> 110080 total
    float* s_atth = s_hid;                    // gate scratch (transposed 64x[129])
    __shared__ int sh_np, sh_t0;

    int tid = threadIdx.x;
    int tile0 = blockIdx.x * 128;
    if (tid < 128) {
        int e = g_perm[tile0 + tid];
        s_src[tid] = edge_index[e];
        s_dst[tid] = edge_index[NE + e];
        s_et[tid]  = edge_type[e];
#pragma unroll
        for (int j = 0; j < D_EF; j++) s_ea[tid * D_EF + j] = edge_attr[e * D_EF + j];
    } else if (tid < 192) {
        s_ba1[tid - 128] = b_att1[l * 64 + (tid - 128)];
    } else {
        s_wa2[tid - 192] = W_att2[l * 64 + (tid - 192)];
    }
    __syncthreads();
    if (tid == 0) {
        int t0 = s_et[0];
        sh_t0 = t0;
        sh_np = (s_et[127] == t0) ? 1 : 2;
    }
    __syncthreads();
    int npasses = sh_np;
    float ba2 = b_att2[l];
    int tx = tid & 15, ty = tid >> 4;

    for (int p = 0; p < npasses; p++) {
        int t = (npasses == 1) ? sh_t0 : p;
        // stage folded edge weights
        for (int idx = tid; idx < D_EF * D_H; idx += 256) s_Wf[idx] = g_Wf[l][t][idx];
        if (tid < D_H) s_bf[tid] = g_bf[l][t][tid];
        // attention gate first (uses s_hid as scratch)
        if (t == 1) {
            for (int idx = tid; idx < 128 * 64; idx += 256) {
                int i = idx >> 6, m = idx & 63;
                int d = s_dst[i], s = s_src[i];
                float v = __ldg(g_P + d * PC + 512 + m) + __ldg(g_P + s * PC + 576 + m) + s_ba1[m];
                s_atth[m * 129 + i] = fmaxf(v, 0.f);
            }
            __syncthreads();
            if (tid < 128) {
                float z = ba2;
#pragma unroll 8
                for (int m = 0; m < 64; m++) z = fmaf(s_atth[m * 129 + tid], s_wa2[m], z);
                s_att[tid] = 1.f / (1.f + expf(-z));
            }
        }
        __syncthreads();
        // phase1: hidden = relu(P_dst + P_src + ea@Wf + bf), float4 per thread
        {
            int q = tid & 31, gi = tid >> 5;
            int k4 = q * 4;
            int cD = t ? 256 : 0;
            float4 bf4 = *(const float4*)(s_bf + k4);
#pragma unroll 2
            for (int i = gi; i < 128; i += 8) {
                int d = s_dst[i], s = s_src[i];
                float4 vd = __ldg((const float4*)(g_P + d * PC + cD + k4));
                float4 vs = __ldg((const float4*)(g_P + s * PC + cD + 128 + k4));
                float a0 = bf4.x + vd.x + vs.x;
                float a1 = bf4.y + vd.y + vs.y;
                float a2v = bf4.z + vd.z + vs.z;
                float a3 = bf4.w + vd.w + vs.w;
#pragma unroll
                for (int j = 0; j < D_EF; j++) {
                    float e = s_ea[i * D_EF + j];
                    float4 w = *(const float4*)(s_Wf + j * D_H + k4);
                    a0 = fmaf(e, w.x, a0); a1 = fmaf(e, w.y, a1);
                    a2v = fmaf(e, w.z, a2v); a3 = fmaf(e, w.w, a3);
                }
                float* hp = s_hid + i * 129 + k4;
                hp[0] = fmaxf(a0, 0.f); hp[1] = fmaxf(a1, 0.f);
                hp[2] = fmaxf(a2v, 0.f); hp[3] = fmaxf(a3, 0.f);
            }
        }
        __syncthreads();
        // GEMM2 with K-split W2 staging
        const float* W2 = (t ? W_eav2 : W_leg2) + l * D_H * D_H;
        const float* b2 = (t ? b_eav2 : b_leg2) + l * D_H;
        u64 acc[8][4];
#pragma unroll
        for (int r = 0; r < 8; r++)
#pragma unroll
            for (int j = 0; j < 4; j++) acc[r][j] = 0ull;
        for (int kk = 0; kk < 2; kk++) {
            for (int idx = tid; idx < 64 * 32; idx += 256) {
                int c = idx >> 5, k4 = (idx & 31) * 4;
                *(float4*)(s_B + c * 128 + k4) = *(const float4*)(W2 + (kk * 64 + c) * D_H + k4);
            }
            __syncthreads();
            mmtile(s_hid + kk * 64, 129, s_B, 64, ty, tx, acc);
            __syncthreads();
        }
        float bias[8];
#pragma unroll
        for (int j = 0; j < 8; j++) bias[j] = b2[tx * 8 + j];
        // scatter-add gated messages
#pragma unroll
        for (int r = 0; r < 8; r++) {
            int i = ty * 8 + r;
            if (npasses == 1 || s_et[i] == t) {
                float sc = t ? s_att[i] : 1.f;
                float o[8];
#pragma unroll
                for (int j = 0; j < 4; j++) unpack2(acc[r][j], o[2 * j], o[2 * j + 1]);
                float* dp = g_aggr + s_dst[i] * D_H + tx * 8;
                red4(dp, make_float4((o[0] + bias[0]) * sc, (o[1] + bias[1]) * sc,
                                     (o[2] + bias[2]) * sc, (o[3] + bias[3]) * sc));
                red4(dp + 4, make_float4((o[4] + bias[4]) * sc, (o[5] + bias[5]) * sc,
                                         (o[6] + bias[6]) * sc, (o[7] + bias[7]) * sc));
            }
        }
        __syncthreads();
    }
}

// ------------------------- k_update: upd MLP + LN(shuffle) + residual --------
__global__ void __launch_bounds__(256, 2) k_update(
    int l, const float* __restrict__ W_upd, const float* __restrict__ b_upd,
    const float* __restrict__ ln_g, const float* __restrict__ ln_b) {
    extern __shared__ __align__(16) float sm[];
    float* sA = sm;               // 128 x 65 (padded)
    float* sB = sm + 128 * 65;    // 64 x 128
    int tid = threadIdx.x;
    int row0 = blockIdx.x * 128;
    int tx = tid & 15, ty = tid >> 4;
    u64 acc[8][4];
#pragma unroll
    for (int r = 0; r < 8; r++)
#pragma unroll
        for (int j = 0; j < 4; j++) acc[r][j] = 0ull;
    const float* W = W_upd + l * 256 * D_H;
    for (int kk = 0; kk < 4; kk++) {
        const float* Asrc = (kk < 2) ? g_x : g_aggr;
        int cbase = (kk & 1) * 64;
        for (int idx = tid; idx < 128 * 64; idx += 256) {
            int i = idx >> 6, c = idx & 63;
            int r = row0 + i;
            sA[i * 65 + c] = (r < NN) ? Asrc[r * D_H + cbase + c] : 0.f;
        }
        for (int idx = tid; idx < 64 * 32; idx += 256) {
            int c = idx >> 5, k4 = (idx & 31) * 4;
            *(float4*)(sB + c * 128 + k4) = *(const float4*)(W + (kk * 64 + c) * D_H + k4);
        }
        __syncthreads();
        mmtile(sA, 65, sB, 64, ty, tx, acc);
        __syncthreads();
    }
    float bias[8], gg[8], bb2[8];
#pragma unroll
    for (int j = 0; j < 8; j++) {
        int col = tx * 8 + j;
        bias[j] = b_upd[l * D_H + col];
        gg[j] = ln_g[l * D_H + col];
        bb2[j] = ln_b[l * D_H + col];
    }
#pragma unroll
    for (int r = 0; r < 8; r++) {
        float o[8];
#pragma unroll
        for (int j = 0; j < 4; j++) unpack2(acc[r][j], o[2 * j], o[2 * j + 1]);
#pragma unroll
        for (int j = 0; j < 8; j++) o[j] += bias[j];
        float s1 = 0.f;
#pragma unroll
        for (int j = 0; j < 8; j++) s1 += o[j];
#pragma unroll
        for (int d = 8; d >= 1; d >>= 1) s1 += __shfl_xor_sync(0xffffffff, s1, d);
        float mu = s1 * (1.f / D_H);
        float s2 = 0.f;
#pragma unroll
        for (int j = 0; j < 8; j++) {
            float dv = o[j] - mu;
            s2 = fmaf(dv, dv, s2);
        }
#pragma unroll
        for (int d = 8; d >= 1; d >>= 1) s2 += __shfl_xor_sync(0xffffffff, s2, d);
        float rs = rsqrtf(s2 * (1.f / D_H) + LN_EPS);
        int row = row0 + ty * 8 + r;
        if (row < NN) {
            float* xp = g_x + row * D_H + tx * 8;
            float4 x0 = *(const float4*)xp;
            float4 x1 = *(const float4*)(xp + 4);
            float xo[8] = {x0.x, x0.y, x0.z, x0.w, x1.x, x1.y, x1.z, x1.w};
            float o2[8];
#pragma unroll
            for (int j = 0; j < 8; j++) {
                float h = (o[j] - mu) * rs * gg[j] + bb2[j];
                o2[j] = fmaxf(fmaxf(h, 0.f) + xo[j], 0.f);
            }
            *(float4*)xp = make_float4(o2[0], o2[1], o2[2], o2[3]);
            *(float4*)(xp + 4) = make_float4(o2[4], o2[5], o2[6], o2[7]);
        }
    }
}

// ------------------------- k_pool -------------------------------------------
__global__ void k_pool() {
    __shared__ float sp[256];
    int tid = threadIdx.x;
    int row0 = blockIdx.x * 64;
    int k = tid & 127, ih = tid >> 7;
    float v = 0.f;
    for (int i = ih; i < 64; i += 2) {
        int r = row0 + i;
        if (r < NN) v += g_x[r * D_H + k];
    }
    sp[tid] = v;
    __syncthreads();
    if (tid < 128) atomicAdd(&g_pool[k], sp[tid] + sp[tid + 128]);
}

// ------------------------- k_head -------------------------------------------
__global__ void k_head(float* out, const float* __restrict__ traj,
                       const float* __restrict__ W_ref1, const float* __restrict__ b_ref1,
                       const float* __restrict__ W_ref2, const float* __restrict__ b_ref2) {
    __shared__ float sg[D_H], sr1[D_H];
    int tid = threadIdx.x; // 128
    sg[tid] = g_pool[tid] * (1.f / NN);
    __syncthreads();
    float acc = b_ref1[tid];
    for (int c = 0; c < D_H; c++) acc = fmaf(sg[c], W_ref1[c * D_H + tid], acc);
    sr1[tid] = fmaxf(acc, 0.f);
    __syncthreads();
    if (tid < D_OUT) {
        float r2 = b_ref2[tid];
        for (int c = 0; c < D_H; c++) r2 = fmaf(sr1[c], W_ref2[c * D_OUT + tid], r2);
        if (tid < 3) out[164 + tid] = traj[tid] + r2;
    }
    out[167 + tid] = sg[tid];
}

// ------------------------- launch ------------------------------------------
extern "C" void kernel_launch(void* const* d_in, const int* in_sizes, int n_in,
                              void* d_out, int out_size) {
    const float* x_in      = (const float*)d_in[0];
    const float* edge_attr = (const float*)d_in[1];
    const int*   edge_index= (const int*)d_in[2];
    const int*   edge_type = (const int*)d_in[3];
    const float* beam      = (const float*)d_in[5];
    const float* ris       = (const float*)d_in[6];
    const float* traj      = (const float*)d_in[7];
    const float* W_node = (const float*)d_in[8];
    const float* b_node = (const float*)d_in[9];
    const float* W_edge = (const float*)d_in[10];
    const float* b_edge = (const float*)d_in[11];
    const float* W_leg1 = (const float*)d_in[12];
    const float* b_leg1 = (const float*)d_in[13];
    const float* W_leg2 = (const float*)d_in[14];
    const float* b_leg2 = (const float*)d_in[15];
    const float* W_eav1 = (const float*)d_in[16];
    const float* b_eav1 = (const float*)d_in[17];
    const float* W_eav2 = (const float*)d_in[18];
    const float* b_eav2 = (const float*)d_in[19];
    const float* W_att1 = (const float*)d_in[20];
    const float* b_att1 = (const float*)d_in[21];
    const float* W_att2 = (const float*)d_in[22];
    const float* b_att2 = (const float*)d_in[23];
    const float* W_upd  = (const float*)d_in[24];
    const float* b_upd  = (const float*)d_in[25];
    const float* ln_g   = (const float*)d_in[26];
    const float* ln_b   = (const float*)d_in[27];
    const float* W_ref1 = (const float*)d_in[28];
    const float* b_ref1 = (const float*)d_in[29];
    const float* W_ref2 = (const float*)d_in[30];
    const float* b_ref2 = (const float*)d_in[31];
    float* out = (float*)d_out;

    const int SMEM_PROJ = (128 * 129 + 64 * 128) * 4;              // 98816
    const int SMEM_EDGE = 110080;
    const int SMEM_UPD  = (128 * 65 + 64 * 128) * 4;               // 66048
    cudaFuncSetAttribute(k_proj,   cudaFuncAttributeMaxDynamicSharedMemorySize, SMEM_PROJ);
    cudaFuncSetAttribute(k_edge,   cudaFuncAttributeMaxDynamicSharedMemorySize, SMEM_EDGE);
    cudaFuncSetAttribute(k_update, cudaFuncAttributeMaxDynamicSharedMemorySize, SMEM_UPD);

    void* aggr_ptr = nullptr;
    cudaGetSymbolAddress(&aggr_ptr, g_aggr);

    k_setup<<<15, 256>>>(out, beam, ris, W_leg1, b_leg1, W_eav1, b_eav1,
                         W_edge, b_edge, W_att1);
    k_partition<<<(NE + 255) / 256, 256>>>(edge_type);
    k_embed<<<NT64, 256>>>(x_in, W_node, b_node);

    for (int l = 0; l < N_L; l++) {
        cudaMemsetAsync(aggr_ptr, 0, (size_t)NN * D_H * sizeof(float));
        k_proj<<<dim3(NT128, 5), 256, SMEM_PROJ>>>(l);
        k_edge<<<NE / 128, 256, SMEM_EDGE>>>(l, edge_index, edge_type, edge_attr,
                                             W_leg2, b_leg2, W_eav2, b_eav2,
                                             W_att2, b_att2, b_att1);
        k_update<<<NT128, 256, SMEM_UPD>>>(l, W_upd, b_upd, ln_g, ln_b);
    }

    k_pool<<<NT64, 256>>>();
    k_head<<<1, 128>>>(out, traj, W_ref1, b_ref1, W_ref2, b_ref2);
}

// round 4
// speedup vs baseline: 2.2297x; 1.0688x over previous
#include <cuda_runtime.h>
#include <math.h>

#define NN 50000
#define NE 400000
#define D_IN 32
#define D_H 128
#define D_EF 8
#define N_L 2
#define D_OUT 16
#define PC 640            // packed per-node projection columns: 4*128 + 2*64
#define NT64 ((NN + 63) / 64)
#define NT128 ((NN + 127) / 128)
#define LN_EPS 1e-5f

typedef unsigned long long u64;

// ------------------------- scratch (device globals) -------------------------
__device__ float g_x[NN * D_H];
__device__ float g_aggr[NN * D_H];
__device__ float g_P[NN * PC];
__device__ float g_Wpack[N_L][D_H * PC];
__device__ float g_Wf[N_L][2][D_EF * D_H];
__device__ float g_bf[N_L][2][D_H];
__device__ int   g_perm[NE];
__device__ int   g_cnt[2];
__device__ float g_pool[D_H];

// ------------------------- packed-fma micro-GEMM helpers --------------------
__device__ __forceinline__ u64 pack2(float a) {
    u64 r;
    unsigned int au = __float_as_uint(a);
    asm("mov.b64 %0, {%1, %1};" : "=l"(r) : "r"(au));
    return r;
}
__device__ __forceinline__ void fma2(u64& d, u64 a, u64 b) {
    asm("fma.rn.f32x2 %0, %1, %2, %0;" : "+l"(d) : "l"(a), "l"(b));
}
__device__ __forceinline__ void unpack2(u64 v, float& lo, float& hi) {
    asm("mov.b64 {%0, %1}, %2;" : "=f"(lo), "=f"(hi) : "l"(v));
}
// C[128x128] += A[128 x K] * B[K x 128]; lda EVEN (float2 A loads, bank-safe),
// K even. K unrolled by 2: 12 LDS per 64 fma2.
__device__ __forceinline__ void mmtile2(const float* sA, int lda, const float* sB, int K,
                                        int ty, int tx, u64 acc[8][4]) {
    for (int c = 0; c < K; c += 2) {
        float2 a2[8];
#pragma unroll
        for (int r = 0; r < 8; r++) a2[r] = *(const float2*)(sA + (ty * 8 + r) * lda + c);
        ulonglong2 b01 = *(const ulonglong2*)(sB + c * 128 + tx * 8);
        ulonglong2 b23 = *(const ulonglong2*)(sB + c * 128 + tx * 8 + 4);
        u64 bb0[4] = {b01.x, b01.y, b23.x, b23.y};
        ulonglong2 c01 = *(const ulonglong2*)(sB + (c + 1) * 128 + tx * 8);
        ulonglong2 c23 = *(const ulonglong2*)(sB + (c + 1) * 128 + tx * 8 + 4);
        u64 bb1[4] = {c01.x, c01.y, c23.x, c23.y};
#pragma unroll
        for (int r = 0; r < 8; r++) {
            u64 ax = pack2(a2[r].x);
#pragma unroll
            for (int j = 0; j < 4; j++) fma2(acc[r][j], ax, bb0[j]);
        }
#pragma unroll
        for (int r = 0; r < 8; r++) {
            u64 ay = pack2(a2[r].y);
#pragma unroll
            for (int j = 0; j < 4; j++) fma2(acc[r][j], ay, bb1[j]);
        }
    }
}

__device__ __forceinline__ void red4(float* p, float4 v) {
    asm volatile("red.global.add.v4.f32 [%0], {%1,%2,%3,%4};"
                 :: "l"(p), "f"(v.x), "f"(v.y), "f"(v.z), "f"(v.w) : "memory");
}

// ------------------------- k_setup: fused zero + fold + pack -----------------
__global__ void __launch_bounds__(256) k_setup(
    float* out, const float* beam, const float* ris,
    const float* __restrict__ W_leg1, const float* __restrict__ b_leg1,
    const float* __restrict__ W_eav1, const float* __restrict__ b_eav1,
    const float* __restrict__ W_edge, const float* __restrict__ b_edge,
    const float* __restrict__ W_att1) {
    int b = blockIdx.x, tid = threadIdx.x;
    if (b == 0) {
        if (tid < 2) g_cnt[tid] = 0;
        if (tid < D_H) g_pool[tid] = 0.f;
        if (tid < 64) out[tid] = beam[tid];
        else if (tid < 164) out[tid] = ris[tid - 64];
        return;
    }
    if (b <= 4) {
        __shared__ float sW[64 * D_H];
        __shared__ float sWe[D_EF * D_H];
        __shared__ float sbe[D_H];
        int l = (b - 1) >> 1, t = (b - 1) & 1;
        const float* W1 = (t ? W_eav1 : W_leg1) + l * 384 * D_H;
        const float* b1 = (t ? b_eav1 : b_leg1) + l * D_H;
        for (int idx = tid; idx < D_EF * D_H; idx += 256) sWe[idx] = W_edge[idx];
        if (tid < D_H) sbe[tid] = b_edge[tid];
        float accb = (tid < D_H) ? b1[tid] : 0.f;
        float accj[D_EF];
#pragma unroll
        for (int j = 0; j < D_EF; j++) accj[j] = 0.f;
        for (int cb = 0; cb < 2; cb++) {
            __syncthreads();
            for (int idx = tid; idx < 64 * D_H; idx += 256)
                sW[idx] = W1[(256 + cb * 64 + (idx >> 7)) * D_H + (idx & 127)];
            __syncthreads();
            if (tid < D_H) {
                for (int c2 = 0; c2 < 64; c2++) {
                    float w = sW[c2 * D_H + tid];
                    int c = cb * 64 + c2;
                    accb = fmaf(sbe[c], w, accb);
#pragma unroll
                    for (int j = 0; j < D_EF; j++) accj[j] = fmaf(sWe[j * D_H + c], w, accj[j]);
                }
            }
        }
        if (tid < D_H) {
            g_bf[l][t][tid] = accb;
#pragma unroll
            for (int j = 0; j < D_EF; j++) g_Wf[l][t][j * D_H + tid] = accj[j];
        }
        return;
    }
    int l = (b - 5) / 5, ch = (b - 5) % 5;
    for (int idx = tid; idx < 128 * 128; idx += 256) {
        int c = idx >> 7, k = idx & 127;
        float v;
        if (ch < 4) {
            const float* W1 = ((ch >> 1) ? W_eav1 : W_leg1) + l * 384 * D_H;
            v = W1[((ch & 1) * 128 + c) * D_H + k];
        } else {
            const float* Wa = W_att1 + l * 256 * 64;
            v = (k < 64) ? Wa[c * 64 + k] : Wa[(128 + c) * 64 + (k - 64)];
        }
        g_Wpack[l][c * PC + ch * 128 + k] = v;
    }
}

// ------------------------- k_partition ---------------------------------------
__global__ void k_partition(const int* __restrict__ edge_type) {
    int e = blockIdx.x * blockDim.x + threadIdx.x;
    if (e >= NE) return;
    int et = edge_type[e];
    int pos = et ? (NE - 1 - atomicAdd(&g_cnt[1], 1)) : atomicAdd(&g_cnt[0], 1);
    g_perm[pos] = e;
}

// ------------------------- k_embed: x = x_in @ W_node + b --------------------
__global__ void __launch_bounds__(256) k_embed(const float* __restrict__ x_in,
                                               const float* __restrict__ W_node,
                                               const float* __restrict__ b_node) {
    __shared__ float sA[64][D_IN + 1];
    __shared__ __align__(16) float sB[D_IN * D_H];
    __shared__ float sb[D_H];
    int tid = threadIdx.x;
    int row0 = blockIdx.x * 64;
    for (int idx = tid; idx < 64 * D_IN; idx += 256) {
        int i = idx >> 5, c = idx & 31;
        int r = row0 + i;
        sA[i][c] = (r < NN) ? x_in[r * D_IN + c] : 0.f;
    }
    for (int idx = tid; idx < D_IN * D_H; idx += 256) sB[idx] = W_node[idx];
    if (tid < D_H) sb[tid] = b_node[tid];
    __syncthreads();
    int tx = tid & 15, ty = tid >> 4;
    float acc[4][8];
#pragma unroll
    for (int r = 0; r < 4; r++)
#pragma unroll
        for (int j = 0; j < 8; j++) acc[r][j] = 0.f;
    for (int c = 0; c < D_IN; c++) {
        float a[4];
#pragma unroll
        for (int r = 0; r < 4; r++) a[r] = sA[ty * 4 + r][c];
        float4 b0 = *(const float4*)(sB + c * D_H + tx * 8);
        float4 b1 = *(const float4*)(sB + c * D_H + tx * 8 + 4);
        float bb[8] = {b0.x, b0.y, b0.z, b0.w, b1.x, b1.y, b1.z, b1.w};
#pragma unroll
        for (int r = 0; r < 4; r++)
#pragma unroll
            for (int j = 0; j < 8; j++) acc[r][j] = fmaf(a[r], bb[j], acc[r][j]);
    }
#pragma unroll
    for (int r = 0; r < 4; r++) {
        int row = row0 + ty * 4 + r;
        if (row < NN) {
#pragma unroll
            for (int j = 0; j < 8; j++) {
                int col = tx * 8 + j;
                g_x[row * D_H + col] = acc[r][j] + sb[col];
            }
        }
    }
}

// ------------------------- k_proj: P = x @ Wpack[l] --------------------------
// sA 128x130 (float2-friendly), sB 64x128 K-chunks; 2 blocks/SM
__global__ void __launch_bounds__(256, 2) k_proj(int l) {
    extern __shared__ __align__(16) float sm[];
    float* sA = sm;               // 128 x 130
    float* sB = sm + 128 * 130;   // 64 x 128
    int tid = threadIdx.x;
    int row0 = blockIdx.x * 128;
    int ch = blockIdx.y;
    const float* Wp = g_Wpack[l];
    for (int idx = tid; idx < 128 * 32; idx += 256) {
        int i = idx >> 5, k4 = (idx & 31) * 4;
        int r = row0 + i;
        float4 v = make_float4(0.f, 0.f, 0.f, 0.f);
        if (r < NN) v = *(const float4*)(g_x + r * D_H + k4);
        float* ap = sA + i * 130 + k4;
        *(float2*)ap = make_float2(v.x, v.y);
        *(float2*)(ap + 2) = make_float2(v.z, v.w);
    }
    int tx = tid & 15, ty = tid >> 4;
    u64 acc[8][4];
#pragma unroll
    for (int r = 0; r < 8; r++)
#pragma unroll
        for (int j = 0; j < 4; j++) acc[r][j] = 0ull;
    for (int kk = 0; kk < 2; kk++) {
        __syncthreads();
        for (int idx = tid; idx < 64 * 32; idx += 256) {
            int c = idx >> 5, k4 = (idx & 31) * 4;
            *(float4*)(sB + c * 128 + k4) = *(const float4*)(Wp + (kk * 64 + c) * PC + ch * 128 + k4);
        }
        __syncthreads();
        mmtile2(sA + kk * 64, 130, sB, 64, ty, tx, acc);
    }
#pragma unroll
    for (int r = 0; r < 8; r++) {
        int row = row0 + ty * 8 + r;
        if (row < NN) {
            float o[8];
#pragma unroll
            for (int j = 0; j < 4; j++) unpack2(acc[r][j], o[2 * j], o[2 * j + 1]);
            float* dp = g_P + row * PC + ch * 128 + tx * 8;
            *(float4*)dp = make_float4(o[0], o[1], o[2], o[3]);
            *(float4*)(dp + 4) = make_float4(o[4], o[5], o[6], o[7]);
        }
    }
}

// ------------------------- k_edge --------------------------------------------
__global__ void __launch_bounds__(256, 2) k_edge(
    int l, const int* __restrict__ edge_index, const int* __restrict__ edge_type,
    const float* __restrict__ edge_attr,
    const float* __restrict__ W_leg2, const float* __restrict__ b_leg2,
    const float* __restrict__ W_eav2, const float* __restrict__ b_eav2,
    const float* __restrict__ W_att2, const float* __restrict__ b_att2,
    const float* __restrict__ b_att1) {
    extern __shared__ __align__(16) char smraw[];
    int* s_dst = (int*)smraw;                 // 128
    int* s_src = (int*)(smraw + 512);         // 128
    int* s_et  = (int*)(smraw + 1024);        // 128
    float* s_ea  = (float*)(smraw + 1536);    // 128*8
    float* s_Wf  = (float*)(smraw + 5632);    // 8*128
    float* s_bf  = (float*)(smraw + 9728);    // 128
    float* s_ba1 = (float*)(smraw + 10240);   // 64
    float* s_wa2 = (float*)(smraw + 10496);   // 64
    float* s_att = (float*)(smraw + 10752);   // 128
    float* s_hid = (float*)(smraw + 11264);   // 128*130*4 = 66560B
    float* s_B   = (float*)(smraw + 77824);   // 64*128*4  = 32768B -> 110592 total
    float* s_atth = s_hid;                    // gate scratch 64x129 overlay
    __shared__ int sh_np, sh_t0;

    int tid = threadIdx.x;
    int tile0 = blockIdx.x * 128;
    if (tid < 128) {
        int e = g_perm[tile0 + tid];
        s_src[tid] = edge_index[e];
        s_dst[tid] = edge_index[NE + e];
        s_et[tid]  = edge_type[e];
#pragma unroll
        for (int j = 0; j < D_EF; j++) s_ea[tid * D_EF + j] = edge_attr[e * D_EF + j];
    } else if (tid < 192) {
        s_ba1[tid - 128] = b_att1[l * 64 + (tid - 128)];
    } else {
        s_wa2[tid - 192] = W_att2[l * 64 + (tid - 192)];
    }
    __syncthreads();
    if (tid == 0) {
        int t0 = s_et[0];
        sh_t0 = t0;
        sh_np = (s_et[127] == t0) ? 1 : 2;
    }
    __syncthreads();
    int npasses = sh_np;
    float ba2 = b_att2[l];
    int tx = tid & 15, ty = tid >> 4;

    for (int p = 0; p < npasses; p++) {
        int t = (npasses == 1) ? sh_t0 : p;
        for (int idx = tid; idx < D_EF * D_H; idx += 256) s_Wf[idx] = g_Wf[l][t][idx];
        if (tid < D_H) s_bf[tid] = g_bf[l][t][tid];
        // attention gate first (uses s_hid as scratch)
        if (t == 1) {
            for (int idx = tid; idx < 128 * 64; idx += 256) {
                int i = idx >> 6, m = idx & 63;
                int d = s_dst[i], s = s_src[i];
                float v = __ldg(g_P + d * PC + 512 + m) + __ldg(g_P + s * PC + 576 + m) + s_ba1[m];
                s_atth[m * 129 + i] = fmaxf(v, 0.f);
            }
            __syncthreads();
            if (tid < 128) {
                float z = ba2;
#pragma unroll 8
                for (int m = 0; m < 64; m++) z = fmaf(s_atth[m * 129 + tid], s_wa2[m], z);
                s_att[tid] = 1.f / (1.f + expf(-z));
            }
        }
        __syncthreads();
        // phase1: hidden = relu(P_dst + P_src + ea@Wf + bf)
        {
            int q = tid & 31, gi = tid >> 5;
            int k4 = q * 4;
            int cD = t ? 256 : 0;
            float4 bf4 = *(const float4*)(s_bf + k4);
#pragma unroll 2
            for (int i = gi; i < 128; i += 8) {
                int d = s_dst[i], s = s_src[i];
                float4 vd = __ldg((const float4*)(g_P + d * PC + cD + k4));
                float4 vs = __ldg((const float4*)(g_P + s * PC + cD + 128 + k4));
                float a0 = bf4.x + vd.x + vs.x;
                float a1 = bf4.y + vd.y + vs.y;
                float a2v = bf4.z + vd.z + vs.z;
                float a3 = bf4.w + vd.w + vs.w;
#pragma unroll
                for (int j = 0; j < D_EF; j++) {
                    float e = s_ea[i * D_EF + j];
                    float4 w = *(const float4*)(s_Wf + j * D_H + k4);
                    a0 = fmaf(e, w.x, a0); a1 = fmaf(e, w.y, a1);
                    a2v = fmaf(e, w.z, a2v); a3 = fmaf(e, w.w, a3);
                }
                float* hp = s_hid + i * 130 + k4;
                *(float2*)hp = make_float2(fmaxf(a0, 0.f), fmaxf(a1, 0.f));
                *(float2*)(hp + 2) = make_float2(fmaxf(a2v, 0.f), fmaxf(a3, 0.f));
            }
        }
        __syncthreads();
        // GEMM2 with K-split W2 staging
        const float* W2 = (t ? W_eav2 : W_leg2) + l * D_H * D_H;
        const float* b2 = (t ? b_eav2 : b_leg2) + l * D_H;
        u64 acc[8][4];
#pragma unroll
        for (int r = 0; r < 8; r++)
#pragma unroll
            for (int j = 0; j < 4; j++) acc[r][j] = 0ull;
        for (int kk = 0; kk < 2; kk++) {
            for (int idx = tid; idx < 64 * 32; idx += 256) {
                int c = idx >> 5, k4 = (idx & 31) * 4;
                *(float4*)(s_B + c * 128 + k4) = *(const float4*)(W2 + (kk * 64 + c) * D_H + k4);
            }
            __syncthreads();
            mmtile2(s_hid + kk * 64, 130, s_B, 64, ty, tx, acc);
            __syncthreads();
        }
        float bias[8];
#pragma unroll
        for (int j = 0; j < 8; j++) bias[j] = b2[tx * 8 + j];
#pragma unroll
        for (int r = 0; r < 8; r++) {
            int i = ty * 8 + r;
            if (npasses == 1 || s_et[i] == t) {
                float sc = t ? s_att[i] : 1.f;
                float o[8];
#pragma unroll
                for (int j = 0; j < 4; j++) unpack2(acc[r][j], o[2 * j], o[2 * j + 1]);
                float* dp = g_aggr + s_dst[i] * D_H + tx * 8;
                red4(dp, make_float4((o[0] + bias[0]) * sc, (o[1] + bias[1]) * sc,
                                     (o[2] + bias[2]) * sc, (o[3] + bias[3]) * sc));
                red4(dp + 4, make_float4((o[4] + bias[4]) * sc, (o[5] + bias[5]) * sc,
                                         (o[6] + bias[6]) * sc, (o[7] + bias[7]) * sc));
            }
        }
        __syncthreads();
    }
}

// ------------------------- k_update: upd MLP + LN(shuffle) + residual --------
__global__ void __launch_bounds__(256, 2) k_update(
    int l, const float* __restrict__ W_upd, const float* __restrict__ b_upd,
    const float* __restrict__ ln_g, const float* __restrict__ ln_b) {
    extern __shared__ __align__(16) float sm[];
    float* sA = sm;               // 128 x 66
    float* sB = sm + 128 * 66;    // 64 x 128
    int tid = threadIdx.x;
    int row0 = blockIdx.x * 128;
    int tx = tid & 15, ty = tid >> 4;
    u64 acc[8][4];
#pragma unroll
    for (int r = 0; r < 8; r++)
#pragma unroll
        for (int j = 0; j < 4; j++) acc[r][j] = 0ull;
    const float* W = W_upd + l * 256 * D_H;
    for (int kk = 0; kk < 4; kk++) {
        const float* Asrc = (kk < 2) ? g_x : g_aggr;
        int cbase = (kk & 1) * 64;
        for (int idx = tid; idx < 128 * 16; idx += 256) {
            int i = idx >> 4, c4 = (idx & 15) * 4;
            int r = row0 + i;
            float4 v = make_float4(0.f, 0.f, 0.f, 0.f);
            if (r < NN) v = *(const float4*)(Asrc + r * D_H + cbase + c4);
            float* ap = sA + i * 66 + c4;
            *(float2*)ap = make_float2(v.x, v.y);
            *(float2*)(ap + 2) = make_float2(v.z, v.w);
        }
        for (int idx = tid; idx < 64 * 32; idx += 256) {
            int c = idx >> 5, k4 = (idx & 31) * 4;
            *(float4*)(sB + c * 128 + k4) = *(const float4*)(W + (kk * 64 + c) * D_H + k4);
        }
        __syncthreads();
        mmtile2(sA, 66, sB, 64, ty, tx, acc);
        __syncthreads();
    }
    float bias[8], gg[8], bb2[8];
#pragma unroll
    for (int j = 0; j < 8; j++) {
        int col = tx * 8 + j;
        bias[j] = b_upd[l * D_H + col];
        gg[j] = ln_g[l * D_H + col];
        bb2[j] = ln_b[l * D_H + col];
    }
#pragma unroll
    for (int r = 0; r < 8; r++) {
        float o[8];
#pragma unroll
        for (int j = 0; j < 4; j++) unpack2(acc[r][j], o[2 * j], o[2 * j + 1]);
#pragma unroll
        for (int j = 0; j < 8; j++) o[j] += bias[j];
        float s1 = 0.f;
#pragma unroll
        for (int j = 0; j < 8; j++) s1 += o[j];
#pragma unroll
        for (int d = 8; d >= 1; d >>= 1) s1 += __shfl_xor_sync(0xffffffff, s1, d);
        float mu = s1 * (1.f / D_H);
        float s2 = 0.f;
#pragma unroll
        for (int j = 0; j < 8; j++) {
            float dv = o[j] - mu;
            s2 = fmaf(dv, dv, s2);
        }
#pragma unroll
        for (int d = 8; d >= 1; d >>= 1) s2 += __shfl_xor_sync(0xffffffff, s2, d);
        float rs = rsqrtf(s2 * (1.f / D_H) + LN_EPS);
        int row = row0 + ty * 8 + r;
        if (row < NN) {
            float* xp = g_x + row * D_H + tx * 8;
            float4 x0 = *(const float4*)xp;
            float4 x1 = *(const float4*)(xp + 4);
            float xo[8] = {x0.x, x0.y, x0.z, x0.w, x1.x, x1.y, x1.z, x1.w};
            float o2[8];
#pragma unroll
            for (int j = 0; j < 8; j++) {
                float h = (o[j] - mu) * rs * gg[j] + bb2[j];
                o2[j] = fmaxf(fmaxf(h, 0.f) + xo[j], 0.f);
            }
            *(float4*)xp = make_float4(o2[0], o2[1], o2[2], o2[3]);
            *(float4*)(xp + 4) = make_float4(o2[4], o2[5], o2[6], o2[7]);
        }
    }
}

// ------------------------- k_pool -------------------------------------------
__global__ void k_pool() {
    __shared__ float sp[256];
    int tid = threadIdx.x;
    int row0 = blockIdx.x * 64;
    int k = tid & 127, ih = tid >> 7;
    float v = 0.f;
    for (int i = ih; i < 64; i += 2) {
        int r = row0 + i;
        if (r < NN) v += g_x[r * D_H + k];
    }
    sp[tid] = v;
    __syncthreads();
    if (tid < 128) atomicAdd(&g_pool[k], sp[tid] + sp[tid + 128]);
}

// ------------------------- k_head -------------------------------------------
__global__ void k_head(float* out, const float* __restrict__ traj,
                       const float* __restrict__ W_ref1, const float* __restrict__ b_ref1,
                       const float* __restrict__ W_ref2, const float* __restrict__ b_ref2) {
    __shared__ float sg[D_H], sr1[D_H];
    int tid = threadIdx.x; // 128
    sg[tid] = g_pool[tid] * (1.f / NN);
    __syncthreads();
    float acc = b_ref1[tid];
    for (int c = 0; c < D_H; c++) acc = fmaf(sg[c], W_ref1[c * D_H + tid], acc);
    sr1[tid] = fmaxf(acc, 0.f);
    __syncthreads();
    if (tid < D_OUT) {
        float r2 = b_ref2[tid];
        for (int c = 0; c < D_H; c++) r2 = fmaf(sr1[c], W_ref2[c * D_OUT + tid], r2);
        if (tid < 3) out[164 + tid] = traj[tid] + r2;
    }
    out[167 + tid] = sg[tid];
}

// ------------------------- launch ------------------------------------------
extern "C" void kernel_launch(void* const* d_in, const int* in_sizes, int n_in,
                              void* d_out, int out_size) {
    const float* x_in      = (const float*)d_in[0];
    const float* edge_attr = (const float*)d_in[1];
    const int*   edge_index= (const int*)d_in[2];
    const int*   edge_type = (const int*)d_in[3];
    const float* beam      = (const float*)d_in[5];
    const float* ris       = (const float*)d_in[6];
    const float* traj      = (const float*)d_in[7];
    const float* W_node = (const float*)d_in[8];
    const float* b_node = (const float*)d_in[9];
    const float* W_edge = (const float*)d_in[10];
    const float* b_edge = (const float*)d_in[11];
    const float* W_leg1 = (const float*)d_in[12];
    const float* b_leg1 = (const float*)d_in[13];
    const float* W_leg2 = (const float*)d_in[14];
    const float* b_leg2 = (const float*)d_in[15];
    const float* W_eav1 = (const float*)d_in[16];
    const float* b_eav1 = (const float*)d_in[17];
    const float* W_eav2 = (const float*)d_in[18];
    const float* b_eav2 = (const float*)d_in[19];
    const float* W_att1 = (const float*)d_in[20];
    const float* b_att1 = (const float*)d_in[21];
    const float* W_att2 = (const float*)d_in[22];
    const float* b_att2 = (const float*)d_in[23];
    const float* W_upd  = (const float*)d_in[24];
    const float* b_upd  = (const float*)d_in[25];
    const float* ln_g   = (const float*)d_in[26];
    const float* ln_b   = (const float*)d_in[27];
    const float* W_ref1 = (const float*)d_in[28];
    const float* b_ref1 = (const float*)d_in[29];
    const float* W_ref2 = (const float*)d_in[30];
    const float* b_ref2 = (const float*)d_in[31];
    float* out = (float*)d_out;

    const int SMEM_PROJ = (128 * 130 + 64 * 128) * 4;              // 99328
    const int SMEM_EDGE = 110592;
    const int SMEM_UPD  = (128 * 66 + 64 * 128) * 4;               // 66560
    cudaFuncSetAttribute(k_proj,   cudaFuncAttributeMaxDynamicSharedMemorySize, SMEM_PROJ);
    cudaFuncSetAttribute(k_edge,   cudaFuncAttributeMaxDynamicSharedMemorySize, SMEM_EDGE);
    cudaFuncSetAttribute(k_update, cudaFuncAttributeMaxDynamicSharedMemorySize, SMEM_UPD);

    void* aggr_ptr = nullptr;
    cudaGetSymbolAddress(&aggr_ptr, g_aggr);

    k_setup<<<15, 256>>>(out, beam, ris, W_leg1, b_leg1, W_eav1, b_eav1,
                         W_edge, b_edge, W_att1);
    k_partition<<<(NE + 255) / 256, 256>>>(edge_type);
    k_embed<<<NT64, 256>>>(x_in, W_node, b_node);

    for (int l = 0; l < N_L; l++) {
        cudaMemsetAsync(aggr_ptr, 0, (size_t)NN * D_H * sizeof(float));
        k_proj<<<dim3(NT128, 5), 256, SMEM_PROJ>>>(l);
        k_edge<<<NE / 128, 256, SMEM_EDGE>>>(l, edge_index, edge_type, edge_attr,
                                             W_leg2, b_leg2, W_eav2, b_eav2,
                                             W_att2, b_att2, b_att1);
        k_update<<<NT128, 256, SMEM_UPD>>>(l, W_upd, b_upd, ln_g, ln_b);
    }

    k_pool<<<NT64, 256>>>();
    k_head<<<1, 128>>>(out, traj, W_ref1, b_ref1, W_ref2, b_ref2);
}

// round 6
// speedup vs baseline: 3.2941x; 1.4774x over previous
#include <cuda_runtime.h>
#include <math.h>
#include <stdint.h>

#define NN 50000
#define NE 400000
#define D_IN 32
#define D_H 128
#define D_EF 8
#define N_L 2
#define D_OUT 16
#define PC 640            // packed per-node projection columns: 4*128 + 2*64
#define NT64 ((NN + 63) / 64)
#define NT128 ((NN + 127) / 128)
#define LN_EPS 1e-5f

typedef unsigned long long u64;

// ------------------------- scratch (device globals) -------------------------
__device__ float g_x[NN * D_H];
__device__ float g_aggr[NN * D_H];
__device__ float g_P[NN * PC];
__device__ float g_WpackT[N_L][5][128 * 128]; // [l][ch][n*128 + k]  (B as [N][K])
__device__ float g_W2T[N_L][2][128 * 128];    // [l][t][n*128 + k]   (W2 transposed)
__device__ float g_Wf[N_L][2][D_EF * D_H];
__device__ float g_bf[N_L][2][D_H];
__device__ int   g_perm[NE];
__device__ int   g_cnt[2];
__device__ float g_pool[D_H];

// ------------------------- packed-fma helpers (k_update/k_embed) ------------
__device__ __forceinline__ u64 pack2(float a) {
    u64 r;
    unsigned int au = __float_as_uint(a);
    asm("mov.b64 %0, {%1, %1};" : "=l"(r) : "r"(au));
    return r;
}
__device__ __forceinline__ void fma2(u64& d, u64 a, u64 b) {
    asm("fma.rn.f32x2 %0, %1, %2, %0;" : "+l"(d) : "l"(a), "l"(b));
}
__device__ __forceinline__ void unpack2(u64 v, float& lo, float& hi) {
    asm("mov.b64 {%0, %1}, %2;" : "=f"(lo), "=f"(hi) : "l"(v));
}
__device__ __forceinline__ void mmtile2(const float* sA, int lda, const float* sB, int K,
                                        int ty, int tx, u64 acc[8][4]) {
    for (int c = 0; c < K; c += 2) {
        float2 a2[8];
#pragma unroll
        for (int r = 0; r < 8; r++) a2[r] = *(const float2*)(sA + (ty * 8 + r) * lda + c);
        ulonglong2 b01 = *(const ulonglong2*)(sB + c * 128 + tx * 8);
        ulonglong2 b23 = *(const ulonglong2*)(sB + c * 128 + tx * 8 + 4);
        u64 bb0[4] = {b01.x, b01.y, b23.x, b23.y};
        ulonglong2 c01 = *(const ulonglong2*)(sB + (c + 1) * 128 + tx * 8);
        ulonglong2 c23 = *(const ulonglong2*)(sB + (c + 1) * 128 + tx * 8 + 4);
        u64 bb1[4] = {c01.x, c01.y, c23.x, c23.y};
#pragma unroll
        for (int r = 0; r < 8; r++) {
            u64 ax = pack2(a2[r].x);
#pragma unroll
            for (int j = 0; j < 4; j++) fma2(acc[r][j], ax, bb0[j]);
        }
#pragma unroll
        for (int r = 0; r < 8; r++) {
            u64 ay = pack2(a2[r].y);
#pragma unroll
            for (int j = 0; j < 4; j++) fma2(acc[r][j], ay, bb1[j]);
        }
    }
}

// ------------------------- tf32 mma helpers ----------------------------------
__device__ __forceinline__ float f2tf32(float f) {
    uint32_t u;
    asm("cvt.rna.tf32.f32 %0, %1;" : "=r"(u) : "f"(f));
    return __uint_as_float(u);
}
__device__ __forceinline__ void mma8(float* c, const uint32_t* a, uint32_t b0, uint32_t b1) {
    asm volatile(
        "mma.sync.aligned.m16n8k8.row.col.f32.tf32.tf32.f32 "
        "{%0,%1,%2,%3}, {%4,%5,%6,%7}, {%8,%9}, {%0,%1,%2,%3};"
        : "+f"(c[0]), "+f"(c[1]), "+f"(c[2]), "+f"(c[3])
        : "r"(a[0]), "r"(a[1]), "r"(a[2]), "r"(a[3]), "r"(b0), "r"(b1));
}
__device__ __forceinline__ void red2(float* p, float x, float y) {
    asm volatile("red.global.add.v2.f32 [%0], {%1,%2};"
                 :: "l"(p), "f"(x), "f"(y) : "memory");
}
__device__ __forceinline__ void red4(float* p, float4 v) {
    asm volatile("red.global.add.v4.f32 [%0], {%1,%2,%3,%4};"
                 :: "l"(p), "f"(v.x), "f"(v.y), "f"(v.z), "f"(v.w) : "memory");
}

#define LDA 132   // 132 mod 32 == 4 -> conflict-free fragment loads
#define LDB 68    // 68  mod 32 == 4

// ------------------------- k_setup: zero + fold + pack -----------------------
// b0: statics; b1-4: fold; b5-14: packT(Wpack); b15-18: pack W2T
__global__ void __launch_bounds__(256) k_setup(
    float* out, const float* beam, const float* ris,
    const float* __restrict__ W_leg1, const float* __restrict__ b_leg1,
    const float* __restrict__ W_eav1, const float* __restrict__ b_eav1,
    const float* __restrict__ W_edge, const float* __restrict__ b_edge,
    const float* __restrict__ W_att1,
    const float* __restrict__ W_leg2, const float* __restrict__ W_eav2) {
    int b = blockIdx.x, tid = threadIdx.x;
    if (b == 0) {
        if (tid < 2) g_cnt[tid] = 0;
        if (tid < D_H) g_pool[tid] = 0.f;
        if (tid < 64) out[tid] = beam[tid];
        else if (tid < 164) out[tid] = ris[tid - 64];
        return;
    }
    if (b <= 4) {
        __shared__ float sW[64 * D_H];
        __shared__ float sWe[D_EF * D_H];
        __shared__ float sbe[D_H];
        int l = (b - 1) >> 1, t = (b - 1) & 1;
        const float* W1 = (t ? W_eav1 : W_leg1) + l * 384 * D_H;
        const float* b1 = (t ? b_eav1 : b_leg1) + l * D_H;
        for (int idx = tid; idx < D_EF * D_H; idx += 256) sWe[idx] = W_edge[idx];
        if (tid < D_H) sbe[tid] = b_edge[tid];
        float accb = (tid < D_H) ? b1[tid] : 0.f;
        float accj[D_EF];
#pragma unroll
        for (int j = 0; j < D_EF; j++) accj[j] = 0.f;
        for (int cb = 0; cb < 2; cb++) {
            __syncthreads();
            for (int idx = tid; idx < 64 * D_H; idx += 256)
                sW[idx] = W1[(256 + cb * 64 + (idx >> 7)) * D_H + (idx & 127)];
            __syncthreads();
            if (tid < D_H) {
                for (int c2 = 0; c2 < 64; c2++) {
                    float w = sW[c2 * D_H + tid];
                    int c = cb * 64 + c2;
                    accb = fmaf(sbe[c], w, accb);
#pragma unroll
                    for (int j = 0; j < D_EF; j++) accj[j] = fmaf(sWe[j * D_H + c], w, accj[j]);
                }
            }
        }
        if (tid < D_H) {
            g_bf[l][t][tid] = accb;
#pragma unroll
            for (int j = 0; j < D_EF; j++) g_Wf[l][t][j * D_H + tid] = accj[j];
        }
        return;
    }
    if (b <= 14) {
        // pack Wpack transposed: [ch][n*128 + k]  (n = output col, k = input)
        int l = (b - 5) / 5, ch = (b - 5) % 5;
        for (int idx = tid; idx < 128 * 128; idx += 256) {
            int k = idx >> 7, n = idx & 127;   // k = input, n = output
            float v;
            if (ch < 4) {
                const float* W1 = ((ch >> 1) ? W_eav1 : W_leg1) + l * 384 * D_H;
                v = W1[((ch & 1) * 128 + k) * D_H + n];
            } else {
                const float* Wa = W_att1 + l * 256 * 64;
                v = (n < 64) ? Wa[k * 64 + n] : Wa[(128 + k) * 64 + (n - 64)];
            }
            g_WpackT[l][ch][n * 128 + k] = v;
        }
        return;
    }
    // pack W2 transposed: [t][n*128 + k]
    {
        int l = (b - 15) >> 1, t = (b - 15) & 1;
        const float* W2 = (t ? W_eav2 : W_leg2) + l * D_H * D_H;
        for (int idx = tid; idx < 128 * 128; idx += 256) {
            int n = idx >> 7, k = idx & 127;
            g_W2T[l][t][n * 128 + k] = W2[k * D_H + n];
        }
    }
}

// ------------------------- k_partition ---------------------------------------
__global__ void k_partition(const int* __restrict__ edge_type) {
    int e = blockIdx.x * blockDim.x + threadIdx.x;
    if (e >= NE) return;
    int et = edge_type[e];
    int pos = et ? (NE - 1 - atomicAdd(&g_cnt[1], 1)) : atomicAdd(&g_cnt[0], 1);
    g_perm[pos] = e;
}

// ------------------------- k_embed: x = x_in @ W_node + b --------------------
__global__ void __launch_bounds__(256) k_embed(const float* __restrict__ x_in,
                                               const float* __restrict__ W_node,
                                               const float* __restrict__ b_node) {
    __shared__ float sA[64][D_IN + 1];
    __shared__ __align__(16) float sB[D_IN * D_H];
    __shared__ float sb[D_H];
    int tid = threadIdx.x;
    int row0 = blockIdx.x * 64;
    for (int idx = tid; idx < 64 * D_IN; idx += 256) {
        int i = idx >> 5, c = idx & 31;
        int r = row0 + i;
        sA[i][c] = (r < NN) ? x_in[r * D_IN + c] : 0.f;
    }
    for (int idx = tid; idx < D_IN * D_H; idx += 256) sB[idx] = W_node[idx];
    if (tid < D_H) sb[tid] = b_node[tid];
    __syncthreads();
    int tx = tid & 15, ty = tid >> 4;
    float acc[4][8];
#pragma unroll
    for (int r = 0; r < 4; r++)
#pragma unroll
        for (int j = 0; j < 8; j++) acc[r][j] = 0.f;
    for (int c = 0; c < D_IN; c++) {
        float a[4];
#pragma unroll
        for (int r = 0; r < 4; r++) a[r] = sA[ty * 4 + r][c];
        float4 b0 = *(const float4*)(sB + c * D_H + tx * 8);
        float4 b1 = *(const float4*)(sB + c * D_H + tx * 8 + 4);
        float bb[8] = {b0.x, b0.y, b0.z, b0.w, b1.x, b1.y, b1.z, b1.w};
#pragma unroll
        for (int r = 0; r < 4; r++)
#pragma unroll
            for (int j = 0; j < 8; j++) acc[r][j] = fmaf(a[r], bb[j], acc[r][j]);
    }
#pragma unroll
    for (int r = 0; r < 4; r++) {
        int row = row0 + ty * 4 + r;
        if (row < NN) {
#pragma unroll
            for (int j = 0; j < 8; j++) {
                int col = tx * 8 + j;
                g_x[row * D_H + col] = acc[r][j] + sb[col];
            }
        }
    }
}

// ------------------------- k_proj_mma: P = x @ Wpack (tf32 mma.sync) ---------
// block tile 128x128, warp tile 32x64 (warps 4x2), K-split B staging.
#define SMEM_PROJ ((128 * LDA + 128 * LDB) * 4)
__global__ void __launch_bounds__(256, 2) k_proj_mma(int l) {
    extern __shared__ __align__(16) float sm[];
    float* sA = sm;               // 128 x LDA
    float* sB = sm + 128 * LDA;   // 128 x LDB (64-k chunk)
    int tid = threadIdx.x;
    int row0 = blockIdx.x * 128;
    int ch = blockIdx.y;
    // stage A (tf32-rounded)
    for (int idx = tid; idx < 128 * 32; idx += 256) {
        int m = idx >> 5, q = (idx & 31) * 4;
        int r = row0 + m;
        float4 v = make_float4(0.f, 0.f, 0.f, 0.f);
        if (r < NN) v = *(const float4*)(g_x + r * D_H + q);
        v.x = f2tf32(v.x); v.y = f2tf32(v.y); v.z = f2tf32(v.z); v.w = f2tf32(v.w);
        *(float4*)(sA + m * LDA + q) = v;
    }
    int wid = tid >> 5, lane = tid & 31;
    int wy = wid >> 1, wx = wid & 1;
    int g = lane >> 2, tig = lane & 3;
    float c[2][8][4];
#pragma unroll
    for (int mt = 0; mt < 2; mt++)
#pragma unroll
        for (int nt = 0; nt < 8; nt++)
#pragma unroll
            for (int j = 0; j < 4; j++) c[mt][nt][j] = 0.f;
    const float* WT = g_WpackT[l][ch];
    for (int chunk = 0; chunk < 2; chunk++) {
        __syncthreads();
        for (int idx = tid; idx < 128 * 16; idx += 256) {
            int n = idx >> 4, q = (idx & 15) * 4;
            float4 v = *(const float4*)(WT + n * 128 + chunk * 64 + q);
            v.x = f2tf32(v.x); v.y = f2tf32(v.y); v.z = f2tf32(v.z); v.w = f2tf32(v.w);
            *(float4*)(sB + n * LDB + q) = v;
        }
        __syncthreads();
#pragma unroll
        for (int ks = 0; ks < 8; ks++) {
            int ka = chunk * 64 + ks * 8 + tig;
            uint32_t a[2][4];
#pragma unroll
            for (int mt = 0; mt < 2; mt++) {
                int base = wy * 32 + mt * 16;
                a[mt][0] = __float_as_uint(sA[(base + g) * LDA + ka]);
                a[mt][1] = __float_as_uint(sA[(base + g + 8) * LDA + ka]);
                a[mt][2] = __float_as_uint(sA[(base + g) * LDA + ka + 4]);
                a[mt][3] = __float_as_uint(sA[(base + g + 8) * LDA + ka + 4]);
            }
#pragma unroll
            for (int nt = 0; nt < 8; nt++) {
                int nb = wx * 64 + nt * 8 + g;
                uint32_t b0 = __float_as_uint(sB[nb * LDB + ks * 8 + tig]);
                uint32_t b1 = __float_as_uint(sB[nb * LDB + ks * 8 + tig + 4]);
                mma8(c[0][nt], a[0], b0, b1);
                mma8(c[1][nt], a[1], b0, b1);
            }
        }
    }
#pragma unroll
    for (int mt = 0; mt < 2; mt++) {
        int r0 = row0 + wy * 32 + mt * 16 + g;
#pragma unroll
        for (int nt = 0; nt < 8; nt++) {
            int col = ch * 128 + wx * 64 + nt * 8 + 2 * tig;
            if (r0 < NN)
                *(float2*)(g_P + (size_t)r0 * PC + col) = make_float2(c[mt][nt][0], c[mt][nt][1]);
            if (r0 + 8 < NN)
                *(float2*)(g_P + (size_t)(r0 + 8) * PC + col) = make_float2(c[mt][nt][2], c[mt][nt][3]);
        }
    }
}

// ------------------------- k_edge: gather + MLP1 + gate + mma GEMM2 + scatter
#define SMEM_EDGE (11264 + 128 * LDA * 4 + 128 * LDB * 4)
__global__ void __launch_bounds__(256, 2) k_edge(
    int l, const int* __restrict__ edge_index, const int* __restrict__ edge_type,
    const float* __restrict__ edge_attr,
    const float* __restrict__ b_leg2, const float* __restrict__ b_eav2,
    const float* __restrict__ W_att2, const float* __restrict__ b_att2,
    const float* __restrict__ b_att1) {
    extern __shared__ __align__(16) char smraw[];
    int* s_dst = (int*)smraw;                 // 128
    int* s_src = (int*)(smraw + 512);         // 128
    int* s_et  = (int*)(smraw + 1024);        // 128
    float* s_ea  = (float*)(smraw + 1536);    // 128*8
    float* s_Wf  = (float*)(smraw + 5632);    // 8*128
    float* s_bf  = (float*)(smraw + 9728);    // 128
    float* s_ba1 = (float*)(smraw + 10240);   // 64
    float* s_wa2 = (float*)(smraw + 10496);   // 64
    float* s_att = (float*)(smraw + 10752);   // 128
    float* s_hid = (float*)(smraw + 11264);   // 128*LDA floats
    float* s_B   = (float*)(smraw + 11264 + 128 * LDA * 4); // 128*LDB floats
    float* s_atth = s_hid;                    // gate scratch 64x129 overlay
    __shared__ int sh_np, sh_t0;

    int tid = threadIdx.x;
    int tile0 = blockIdx.x * 128;
    if (tid < 128) {
        int e = g_perm[tile0 + tid];
        s_src[tid] = edge_index[e];
        s_dst[tid] = edge_index[NE + e];
        s_et[tid]  = edge_type[e];
#pragma unroll
        for (int j = 0; j < D_EF; j++) s_ea[tid * D_EF + j] = edge_attr[e * D_EF + j];
    } else if (tid < 192) {
        s_ba1[tid - 128] = b_att1[l * 64 + (tid - 128)];
    } else {
        s_wa2[tid - 192] = W_att2[l * 64 + (tid - 192)];
    }
    __syncthreads();
    if (tid == 0) {
        int t0 = s_et[0];
        sh_t0 = t0;
        sh_np = (s_et[127] == t0) ? 1 : 2;
    }
    __syncthreads();
    int npasses = sh_np;
    float ba2 = b_att2[l];
    int wid = tid >> 5, lane = tid & 31;
    int wy = wid >> 1, wx = wid & 1;
    int g = lane >> 2, tig = lane & 3;

    for (int p = 0; p < npasses; p++) {
        int t = (npasses == 1) ? sh_t0 : p;
        for (int idx = tid; idx < D_EF * D_H; idx += 256) s_Wf[idx] = g_Wf[l][t][idx];
        if (tid < D_H) s_bf[tid] = g_bf[l][t][tid];
        // attention gate first (uses s_hid as scratch)
        if (t == 1) {
            for (int idx = tid; idx < 128 * 64; idx += 256) {
                int i = idx >> 6, m = idx & 63;
                int d = s_dst[i], s = s_src[i];
                float v = __ldg(g_P + (size_t)d * PC + 512 + m) +
                          __ldg(g_P + (size_t)s * PC + 576 + m) + s_ba1[m];
                s_atth[m * 129 + i] = fmaxf(v, 0.f);
            }
            __syncthreads();
            if (tid < 128) {
                float z = ba2;
#pragma unroll 8
                for (int m = 0; m < 64; m++) z = fmaf(s_atth[m * 129 + tid], s_wa2[m], z);
                s_att[tid] = 1.f / (1.f + expf(-z));
            }
        }
        __syncthreads();
        // phase1: hidden = relu(P_dst + P_src + ea@Wf + bf)  (tf32-rounded)
        {
            int q = tid & 31, gi = tid >> 5;
            int k4 = q * 4;
            int cD = t ? 256 : 0;
            float4 bf4 = *(const float4*)(s_bf + k4);
#pragma unroll 2
            for (int i = gi; i < 128; i += 8) {
                int d = s_dst[i], s = s_src[i];
                float4 vd = __ldg((const float4*)(g_P + (size_t)d * PC + cD + k4));
                float4 vs = __ldg((const float4*)(g_P + (size_t)s * PC + cD + 128 + k4));
                float a0 = bf4.x + vd.x + vs.x;
                float a1 = bf4.y + vd.y + vs.y;
                float a2v = bf4.z + vd.z + vs.z;
                float a3 = bf4.w + vd.w + vs.w;
#pragma unroll
                for (int j = 0; j < D_EF; j++) {
                    float e = s_ea[i * D_EF + j];
                    float4 w = *(const float4*)(s_Wf + j * D_H + k4);
                    a0 = fmaf(e, w.x, a0); a1 = fmaf(e, w.y, a1);
                    a2v = fmaf(e, w.z, a2v); a3 = fmaf(e, w.w, a3);
                }
                float* hp = s_hid + i * LDA + k4;
                *(float2*)hp = make_float2(f2tf32(fmaxf(a0, 0.f)), f2tf32(fmaxf(a1, 0.f)));
                *(float2*)(hp + 2) = make_float2(f2tf32(fmaxf(a2v, 0.f)), f2tf32(fmaxf(a3, 0.f)));
            }
        }
        // GEMM2 via tf32 mma, K-split B staging
        const float* W2T = g_W2T[l][t];
        const float* b2 = (t ? b_eav2 : b_leg2) + l * D_H;
        float c[2][8][4];
#pragma unroll
        for (int mt = 0; mt < 2; mt++)
#pragma unroll
            for (int nt = 0; nt < 8; nt++)
#pragma unroll
                for (int j = 0; j < 4; j++) c[mt][nt][j] = 0.f;
        for (int chunk = 0; chunk < 2; chunk++) {
            __syncthreads();
            for (int idx = tid; idx < 128 * 16; idx += 256) {
                int n = idx >> 4, q = (idx & 15) * 4;
                float4 v = *(const float4*)(W2T + n * 128 + chunk * 64 + q);
                v.x = f2tf32(v.x); v.y = f2tf32(v.y); v.z = f2tf32(v.z); v.w = f2tf32(v.w);
                *(float4*)(s_B + n * LDB + q) = v;
            }
            __syncthreads();
#pragma unroll
            for (int ks = 0; ks < 8; ks++) {
                int ka = chunk * 64 + ks * 8 + tig;
                uint32_t a[2][4];
#pragma unroll
                for (int mt = 0; mt < 2; mt++) {
                    int base = wy * 32 + mt * 16;
                    a[mt][0] = __float_as_uint(s_hid[(base + g) * LDA + ka]);
                    a[mt][1] = __float_as_uint(s_hid[(base + g + 8) * LDA + ka]);
                    a[mt][2] = __float_as_uint(s_hid[(base + g) * LDA + ka + 4]);
                    a[mt][3] = __float_as_uint(s_hid[(base + g + 8) * LDA + ka + 4]);
                }
#pragma unroll
                for (int nt = 0; nt < 8; nt++) {
                    int nb = wx * 64 + nt * 8 + g;
                    uint32_t b0 = __float_as_uint(s_B[nb * LDB + ks * 8 + tig]);
                    uint32_t b1 = __float_as_uint(s_B[nb * LDB + ks * 8 + tig + 4]);
                    mma8(c[0][nt], a[0], b0, b1);
                    mma8(c[1][nt], a[1], b0, b1);
                }
            }
        }
        // epilogue: bias + gate + scatter red.v2
#pragma unroll
        for (int mt = 0; mt < 2; mt++) {
            int i0 = wy * 32 + mt * 16 + g;
            int i1 = i0 + 8;
            bool p0 = (npasses == 1) || (s_et[i0] == t);
            bool p1 = (npasses == 1) || (s_et[i1] == t);
            float sc0 = t ? s_att[i0] : 1.f;
            float sc1 = t ? s_att[i1] : 1.f;
            int d0 = s_dst[i0], d1 = s_dst[i1];
#pragma unroll
            for (int nt = 0; nt < 8; nt++) {
                int col = wx * 64 + nt * 8 + 2 * tig;
                float2 bv = *(const float2*)(b2 + col);
                if (p0) red2(g_aggr + (size_t)d0 * D_H + col,
                             (c[mt][nt][0] + bv.x) * sc0, (c[mt][nt][1] + bv.y) * sc0);
                if (p1) red2(g_aggr + (size_t)d1 * D_H + col,
                             (c[mt][nt][2] + bv.x) * sc1, (c[mt][nt][3] + bv.y) * sc1);
            }
        }
        __syncthreads();
    }
}

// ------------------------- k_update: upd MLP + LN(shuffle) + residual --------
__global__ void __launch_bounds__(256, 2) k_update(
    int l, const float* __restrict__ W_upd, const float* __restrict__ b_upd,
    const float* __restrict__ ln_g, const float* __restrict__ ln_b) {
    extern __shared__ __align__(16) float sm[];
    float* sA = sm;               // 128 x 66
    float* sB = sm + 128 * 66;    // 64 x 128
    int tid = threadIdx.x;
    int row0 = blockIdx.x * 128;
    int tx = tid & 15, ty = tid >> 4;
    u64 acc[8][4];
#pragma unroll
    for (int r = 0; r < 8; r++)
#pragma unroll
        for (int j = 0; j < 4; j++) acc[r][j] = 0ull;
    const float* W = W_upd + l * 256 * D_H;
    for (int kk = 0; kk < 4; kk++) {
        const float* Asrc = (kk < 2) ? g_x : g_aggr;
        int cbase = (kk & 1) * 64;
        for (int idx = tid; idx < 128 * 16; idx += 256) {
            int i = idx >> 4, c4 = (idx & 15) * 4;
            int r = row0 + i;
            float4 v = make_float4(0.f, 0.f, 0.f, 0.f);
            if (r < NN) v = *(const float4*)(Asrc + r * D_H + cbase + c4);
            float* ap = sA + i * 66 + c4;
            *(float2*)ap = make_float2(v.x, v.y);
            *(float2*)(ap + 2) = make_float2(v.z, v.w);
        }
        for (int idx = tid; idx < 64 * 32; idx += 256) {
            int c = idx >> 5, k4 = (idx & 31) * 4;
            *(float4*)(sB + c * 128 + k4) = *(const float4*)(W + (kk * 64 + c) * D_H + k4);
        }
        __syncthreads();
        mmtile2(sA, 66, sB, 64, ty, tx, acc);
        __syncthreads();
    }
    float bias[8], gg[8], bb2[8];
#pragma unroll
    for (int j = 0; j < 8; j++) {
        int col = tx * 8 + j;
        bias[j] = b_upd[l * D_H + col];
        gg[j] = ln_g[l * D_H + col];
        bb2[j] = ln_b[l * D_H + col];
    }
#pragma unroll
    for (int r = 0; r < 8; r++) {
        float o[8];
#pragma unroll
        for (int j = 0; j < 4; j++) unpack2(acc[r][j], o[2 * j], o[2 * j + 1]);
#pragma unroll
        for (int j = 0; j < 8; j++) o[j] += bias[j];
        float s1 = 0.f;
#pragma unroll
        for (int j = 0; j < 8; j++) s1 += o[j];
#pragma unroll
        for (int d = 8; d >= 1; d >>= 1) s1 += __shfl_xor_sync(0xffffffff, s1, d);
        float mu = s1 * (1.f / D_H);
        float s2 = 0.f;
#pragma unroll
        for (int j = 0; j < 8; j++) {
            float dv = o[j] - mu;
            s2 = fmaf(dv, dv, s2);
        }
#pragma unroll
        for (int d = 8; d >= 1; d >>= 1) s2 += __shfl_xor_sync(0xffffffff, s2, d);
        float rs = rsqrtf(s2 * (1.f / D_H) + LN_EPS);
        int row = row0 + ty * 8 + r;
        if (row < NN) {
            float* xp = g_x + row * D_H + tx * 8;
            float4 x0 = *(const float4*)xp;
            float4 x1 = *(const float4*)(xp + 4);
            float xo[8] = {x0.x, x0.y, x0.z, x0.w, x1.x, x1.y, x1.z, x1.w};
            float o2[8];
#pragma unroll
            for (int j = 0; j < 8; j++) {
                float h = (o[j] - mu) * rs * gg[j] + bb2[j];
                o2[j] = fmaxf(fmaxf(h, 0.f) + xo[j], 0.f);
            }
            *(float4*)xp = make_float4(o2[0], o2[1], o2[2], o2[3]);
            *(float4*)(xp + 4) = make_float4(o2[4], o2[5], o2[6], o2[7]);
        }
    }
}

// ------------------------- k_pool -------------------------------------------
__global__ void k_pool() {
    __shared__ float sp[256];
    int tid = threadIdx.x;
    int row0 = blockIdx.x * 64;
    int k = tid & 127, ih = tid >> 7;
    float v = 0.f;
    for (int i = ih; i < 64; i += 2) {
        int r = row0 + i;
        if (r < NN) v += g_x[r * D_H + k];
    }
    sp[tid] = v;
    __syncthreads();
    if (tid < 128) atomicAdd(&g_pool[k], sp[tid] + sp[tid + 128]);
}

// ------------------------- k_head -------------------------------------------
__global__ void k_head(float* out, const float* __restrict__ traj,
                       const float* __restrict__ W_ref1, const float* __restrict__ b_ref1,
                       const float* __restrict__ W_ref2, const float* __restrict__ b_ref2) {
    __shared__ float sg[D_H], sr1[D_H];
    int tid = threadIdx.x; // 128
    sg[tid] = g_pool[tid] * (1.f / NN);
    __syncthreads();
    float acc = b_ref1[tid];
    for (int c = 0; c < D_H; c++) acc = fmaf(sg[c], W_ref1[c * D_H + tid], acc);
    sr1[tid] = fmaxf(acc, 0.f);
    __syncthreads();
    if (tid < D_OUT) {
        float r2 = b_ref2[tid];
        for (int c = 0; c < D_H; c++) r2 = fmaf(sr1[c], W_ref2[c * D_OUT + tid], r2);
        if (tid < 3) out[164 + tid] = traj[tid] + r2;
    }
    out[167 + tid] = sg[tid];
}

// ------------------------- launch ------------------------------------------
extern "C" void kernel_launch(void* const* d_in, const int* in_sizes, int n_in,
                              void* d_out, int out_size) {
    const float* x_in      = (const float*)d_in[0];
    const float* edge_attr = (const float*)d_in[1];
    const int*   edge_index= (const int*)d_in[2];
    const int*   edge_type = (const int*)d_in[3];
    const float* beam      = (const float*)d_in[5];
    const float* ris       = (const float*)d_in[6];
    const float* traj      = (const float*)d_in[7];
    const float* W_node = (const float*)d_in[8];
    const float* b_node = (const float*)d_in[9];
    const float* W_edge = (const float*)d_in[10];
    const float* b_edge = (const float*)d_in[11];
    const float* W_leg1 = (const float*)d_in[12];
    const float* b_leg1 = (const float*)d_in[13];
    const float* W_leg2 = (const float*)d_in[14];
    const float* b_leg2 = (const float*)d_in[15];
    const float* W_eav1 = (const float*)d_in[16];
    const float* b_eav1 = (const float*)d_in[17];
    const float* W_eav2 = (const float*)d_in[18];
    const float* b_eav2 = (const float*)d_in[19];
    const float* W_att1 = (const float*)d_in[20];
    const float* b_att1 = (const float*)d_in[21];
    const float* W_att2 = (const float*)d_in[22];
    const float* b_att2 = (const float*)d_in[23];
    const float* W_upd  = (const float*)d_in[24];
    const float* b_upd  = (const float*)d_in[25];
    const float* ln_g   = (const float*)d_in[26];
    const float* ln_b   = (const float*)d_in[27];
    const float* W_ref1 = (const float*)d_in[28];
    const float* b_ref1 = (const float*)d_in[29];
    const float* W_ref2 = (const float*)d_in[30];
    const float* b_ref2 = (const float*)d_in[31];
    float* out = (float*)d_out;

    const int SMEM_UPD = (128 * 66 + 64 * 128) * 4;  // 66560
    cudaFuncSetAttribute(k_proj_mma, cudaFuncAttributeMaxDynamicSharedMemorySize, SMEM_PROJ);
    cudaFuncSetAttribute(k_edge,     cudaFuncAttributeMaxDynamicSharedMemorySize, SMEM_EDGE);
    cudaFuncSetAttribute(k_update,   cudaFuncAttributeMaxDynamicSharedMemorySize, SMEM_UPD);

    void* aggr_ptr = nullptr;
    cudaGetSymbolAddress(&aggr_ptr, g_aggr);

    k_setup<<<19, 256>>>(out, beam, ris, W_leg1, b_leg1, W_eav1, b_eav1,
                         W_edge, b_edge, W_att1, W_leg2, W_eav2);
    k_partition<<<(NE + 255) / 256, 256>>>(edge_type);
    k_embed<<<NT64, 256>>>(x_in, W_node, b_node);

    for (int l = 0; l < N_L; l++) {
        cudaMemsetAsync(aggr_ptr, 0, (size_t)NN * D_H * sizeof(float));
        k_proj_mma<<<dim3(NT128, 5), 256, SMEM_PROJ>>>(l);
        k_edge<<<NE / 128, 256, SMEM_EDGE>>>(l, edge_index, edge_type, edge_attr,
                                             b_leg2, b_eav2, W_att2, b_att2, b_att1);
        k_update<<<NT128, 256, SMEM_UPD>>>(l, W_upd, b_upd, ln_g, ln_b);
    }

    k_pool<<<NT64, 256>>>();
    k_head<<<1, 128>>>(out, traj, W_ref1, b_ref1, W_ref2, b_ref2);
}

// round 7
// speedup vs baseline: 3.5689x; 1.0834x over previous
#include <cuda_runtime.h>
#include <math.h>
#include <stdint.h>

#define NN 50000
#define NE 400000
#define D_IN 32
#define D_H 128
#define D_EF 8
#define N_L 2
#define D_OUT 16
#define PC 640
#define NT64 ((NN + 63) / 64)
#define LN_EPS 1e-5f

// ------------------------- scratch (device globals) -------------------------
__device__ float g_x[NN * D_H];
__device__ float g_aggr[NN * D_H];
__device__ float g_P[NN * PC];
__device__ float g_WpackT[N_L][5][128 * 128]; // [l][ch][n*128 + k]
__device__ float g_W2T[N_L][2][128 * 128];    // [l][t][n*128 + k]
__device__ float g_WuT[N_L][128 * 256];       // [l][n*256 + k]
__device__ float g_Wf[N_L][2][D_EF * D_H];
__device__ float g_bf[N_L][2][D_H];
__device__ int   g_perm[NE];
__device__ int   g_cnt[2];
__device__ float g_pool[D_H];

// ------------------------- tf32 mma helpers ----------------------------------
__device__ __forceinline__ float f2tf32(float f) {
    uint32_t u;
    asm("cvt.rna.tf32.f32 %0, %1;" : "=r"(u) : "f"(f));
    return __uint_as_float(u);
}
__device__ __forceinline__ void mma8(float* c, const uint32_t* a, uint32_t b0, uint32_t b1) {
    asm volatile(
        "mma.sync.aligned.m16n8k8.row.col.f32.tf32.tf32.f32 "
        "{%0,%1,%2,%3}, {%4,%5,%6,%7}, {%8,%9}, {%0,%1,%2,%3};"
        : "+f"(c[0]), "+f"(c[1]), "+f"(c[2]), "+f"(c[3])
        : "r"(a[0]), "r"(a[1]), "r"(a[2]), "r"(a[3]), "r"(b0), "r"(b1));
}
__device__ __forceinline__ void red2(float* p, float x, float y) {
    asm volatile("red.global.add.v2.f32 [%0], {%1,%2};"
                 :: "l"(p), "f"(x), "f"(y) : "memory");
}

// ------------------------- k_setup: zero + fold + packs ----------------------
// b0 statics; b1-4 fold; b5-14 WpackT; b15-18 W2T; b19-20 WuT
__global__ void __launch_bounds__(256) k_setup(
    float* out, const float* beam, const float* ris,
    const float* __restrict__ W_leg1, const float* __restrict__ b_leg1,
    const float* __restrict__ W_eav1, const float* __restrict__ b_eav1,
    const float* __restrict__ W_edge, const float* __restrict__ b_edge,
    const float* __restrict__ W_att1,
    const float* __restrict__ W_leg2, const float* __restrict__ W_eav2,
    const float* __restrict__ W_upd) {
    int b = blockIdx.x, tid = threadIdx.x;
    if (b == 0) {
        if (tid < 2) g_cnt[tid] = 0;
        if (tid < D_H) g_pool[tid] = 0.f;
        if (tid < 64) out[tid] = beam[tid];
        else if (tid < 164) out[tid] = ris[tid - 64];
        return;
    }
    if (b <= 4) {
        __shared__ float sW[64 * D_H];
        __shared__ float sWe[D_EF * D_H];
        __shared__ float sbe[D_H];
        int l = (b - 1) >> 1, t = (b - 1) & 1;
        const float* W1 = (t ? W_eav1 : W_leg1) + l * 384 * D_H;
        const float* b1 = (t ? b_eav1 : b_leg1) + l * D_H;
        for (int idx = tid; idx < D_EF * D_H; idx += 256) sWe[idx] = W_edge[idx];
        if (tid < D_H) sbe[tid] = b_edge[tid];
        float accb = (tid < D_H) ? b1[tid] : 0.f;
        float accj[D_EF];
#pragma unroll
        for (int j = 0; j < D_EF; j++) accj[j] = 0.f;
        for (int cb = 0; cb < 2; cb++) {
            __syncthreads();
            for (int idx = tid; idx < 64 * D_H; idx += 256)
                sW[idx] = W1[(256 + cb * 64 + (idx >> 7)) * D_H + (idx & 127)];
            __syncthreads();
            if (tid < D_H) {
                for (int c2 = 0; c2 < 64; c2++) {
                    float w = sW[c2 * D_H + tid];
                    int c = cb * 64 + c2;
                    accb = fmaf(sbe[c], w, accb);
#pragma unroll
                    for (int j = 0; j < D_EF; j++) accj[j] = fmaf(sWe[j * D_H + c], w, accj[j]);
                }
            }
        }
        if (tid < D_H) {
            g_bf[l][t][tid] = accb;
#pragma unroll
            for (int j = 0; j < D_EF; j++) g_Wf[l][t][j * D_H + tid] = accj[j];
        }
        return;
    }
    if (b <= 14) {
        int l = (b - 5) / 5, ch = (b - 5) % 5;
        for (int idx = tid; idx < 128 * 128; idx += 256) {
            int k = idx >> 7, n = idx & 127;
            float v;
            if (ch < 4) {
                const float* W1 = ((ch >> 1) ? W_eav1 : W_leg1) + l * 384 * D_H;
                v = W1[((ch & 1) * 128 + k) * D_H + n];
            } else {
                const float* Wa = W_att1 + l * 256 * 64;
                v = (n < 64) ? Wa[k * 64 + n] : Wa[(128 + k) * 64 + (n - 64)];
            }
            g_WpackT[l][ch][n * 128 + k] = v;
        }
        return;
    }
    if (b <= 18) {
        int l = (b - 15) >> 1, t = (b - 15) & 1;
        const float* W2 = (t ? W_eav2 : W_leg2) + l * D_H * D_H;
        for (int idx = tid; idx < 128 * 128; idx += 256) {
            int n = idx >> 7, k = idx & 127;
            g_W2T[l][t][n * 128 + k] = W2[k * D_H + n];
        }
        return;
    }
    {
        int l = b - 19;
        const float* Wu = W_upd + l * 256 * D_H;
        for (int idx = tid; idx < 128 * 256; idx += 256) {
            int n = idx >> 8, k = idx & 255;
            g_WuT[l][n * 256 + k] = Wu[k * D_H + n];
        }
    }
}

// ------------------------- k_partition ---------------------------------------
__global__ void k_partition(const int* __restrict__ edge_type) {
    int e = blockIdx.x * blockDim.x + threadIdx.x;
    if (e >= NE) return;
    int et = edge_type[e];
    int pos = et ? (NE - 1 - atomicAdd(&g_cnt[1], 1)) : atomicAdd(&g_cnt[0], 1);
    g_perm[pos] = e;
}

// ------------------------- k_embed: x = x_in @ W_node + b --------------------
__global__ void __launch_bounds__(256) k_embed(const float* __restrict__ x_in,
                                               const float* __restrict__ W_node,
                                               const float* __restrict__ b_node) {
    __shared__ float sA[64][D_IN + 1];
    __shared__ __align__(16) float sB[D_IN * D_H];
    __shared__ float sb[D_H];
    int tid = threadIdx.x;
    int row0 = blockIdx.x * 64;
    for (int idx = tid; idx < 64 * D_IN; idx += 256) {
        int i = idx >> 5, c = idx & 31;
        int r = row0 + i;
        sA[i][c] = (r < NN) ? x_in[r * D_IN + c] : 0.f;
    }
    for (int idx = tid; idx < D_IN * D_H; idx += 256) sB[idx] = W_node[idx];
    if (tid < D_H) sb[tid] = b_node[tid];
    __syncthreads();
    int tx = tid & 15, ty = tid >> 4;
    float acc[4][8];
#pragma unroll
    for (int r = 0; r < 4; r++)
#pragma unroll
        for (int j = 0; j < 8; j++) acc[r][j] = 0.f;
    for (int c = 0; c < D_IN; c++) {
        float a[4];
#pragma unroll
        for (int r = 0; r < 4; r++) a[r] = sA[ty * 4 + r][c];
        float4 b0 = *(const float4*)(sB + c * D_H + tx * 8);
        float4 b1 = *(const float4*)(sB + c * D_H + tx * 8 + 4);
        float bb[8] = {b0.x, b0.y, b0.z, b0.w, b1.x, b1.y, b1.z, b1.w};
#pragma unroll
        for (int r = 0; r < 4; r++)
#pragma unroll
            for (int j = 0; j < 8; j++) acc[r][j] = fmaf(a[r], bb[j], acc[r][j]);
    }
#pragma unroll
    for (int r = 0; r < 4; r++) {
        int row = row0 + ty * 4 + r;
        if (row < NN) {
#pragma unroll
            for (int j = 0; j < 8; j++) {
                int col = tx * 8 + j;
                g_x[row * D_H + col] = acc[r][j] + sb[col];
            }
        }
    }
}

// ------------------------- k_proj_mma: 64-row tiles, 4 blocks/SM -------------
// block tile 64x128, warps 2x4 (warp tile 32x32), K-chunked A and B.
#define SMEM_PROJ ((64 * 68 + 128 * 68) * 4)
__global__ void __launch_bounds__(256, 4) k_proj_mma(int l) {
    extern __shared__ __align__(16) float sm[];
    float* sA = sm;              // 64 x 68
    float* sB = sm + 64 * 68;    // 128 x 68
    int tid = threadIdx.x;
    int row0 = blockIdx.x * 64;
    int ch = blockIdx.y;
    int wid = tid >> 5, lane = tid & 31;
    int wy = wid >> 2, wx = wid & 3;
    int g = lane >> 2, tig = lane & 3;
    const float* WT = g_WpackT[l][ch];
    float c[2][4][4];
#pragma unroll
    for (int mt = 0; mt < 2; mt++)
#pragma unroll
        for (int nt = 0; nt < 4; nt++)
#pragma unroll
            for (int j = 0; j < 4; j++) c[mt][nt][j] = 0.f;
    for (int chunk = 0; chunk < 2; chunk++) {
        __syncthreads();
        for (int idx = tid; idx < 64 * 16; idx += 256) {
            int m = idx >> 4, q4 = (idx & 15) * 4;
            int r = row0 + m;
            float4 v = make_float4(0.f, 0.f, 0.f, 0.f);
            if (r < NN) v = *(const float4*)(g_x + r * D_H + chunk * 64 + q4);
            v.x = f2tf32(v.x); v.y = f2tf32(v.y); v.z = f2tf32(v.z); v.w = f2tf32(v.w);
            *(float4*)(sA + m * 68 + q4) = v;
        }
        for (int idx = tid; idx < 128 * 16; idx += 256) {
            int n = idx >> 4, q4 = (idx & 15) * 4;
            float4 v = *(const float4*)(WT + n * 128 + chunk * 64 + q4);
            v.x = f2tf32(v.x); v.y = f2tf32(v.y); v.z = f2tf32(v.z); v.w = f2tf32(v.w);
            *(float4*)(sB + n * 68 + q4) = v;
        }
        __syncthreads();
#pragma unroll
        for (int ks = 0; ks < 8; ks++) {
            int ka = ks * 8 + tig;
            uint32_t a[2][4];
#pragma unroll
            for (int mt = 0; mt < 2; mt++) {
                int base = wy * 32 + mt * 16;
                a[mt][0] = __float_as_uint(sA[(base + g) * 68 + ka]);
                a[mt][1] = __float_as_uint(sA[(base + g + 8) * 68 + ka]);
                a[mt][2] = __float_as_uint(sA[(base + g) * 68 + ka + 4]);
                a[mt][3] = __float_as_uint(sA[(base + g + 8) * 68 + ka + 4]);
            }
#pragma unroll
            for (int nt = 0; nt < 4; nt++) {
                int nb = wx * 32 + nt * 8 + g;
                uint32_t b0 = __float_as_uint(sB[nb * 68 + ka]);
                uint32_t b1 = __float_as_uint(sB[nb * 68 + ka + 4]);
                mma8(c[0][nt], a[0], b0, b1);
                mma8(c[1][nt], a[1], b0, b1);
            }
        }
    }
#pragma unroll
    for (int mt = 0; mt < 2; mt++) {
        int r0 = row0 + wy * 32 + mt * 16 + g;
#pragma unroll
        for (int nt = 0; nt < 4; nt++) {
            int col = ch * 128 + wx * 32 + nt * 8 + 2 * tig;
            if (r0 < NN)
                *(float2*)(g_P + (size_t)r0 * PC + col) = make_float2(c[mt][nt][0], c[mt][nt][1]);
            if (r0 + 8 < NN)
                *(float2*)(g_P + (size_t)(r0 + 8) * PC + col) = make_float2(c[mt][nt][2], c[mt][nt][3]);
        }
    }
}

// ------------------------- k_edge: 64-edge tiles, 3 blocks/SM ----------------
// smem map (bytes):
// 0 s_dst[64] | 256 s_src | 512 s_et | 768 s_att | 1024 s_ea(2048) |
// 3072 s_Wf(4096) | 7168 s_bf(512) | 7680 s_ba1(256) | 7936 s_wa2(256) |
// 8192 s_hid 64x132(33792) | 41984 s_B 128x36(18432) -> 60416
#define SMEM_EDGE 60416
__global__ void __launch_bounds__(256, 3) k_edge(
    int l, const int* __restrict__ edge_index, const int* __restrict__ edge_type,
    const float* __restrict__ edge_attr,
    const float* __restrict__ b_leg2, const float* __restrict__ b_eav2,
    const float* __restrict__ W_att2, const float* __restrict__ b_att2,
    const float* __restrict__ b_att1) {
    extern __shared__ __align__(16) char smraw[];
    int* s_dst = (int*)smraw;
    int* s_src = (int*)(smraw + 256);
    int* s_et  = (int*)(smraw + 512);
    float* s_att = (float*)(smraw + 768);
    float* s_ea  = (float*)(smraw + 1024);
    float* s_Wf  = (float*)(smraw + 3072);
    float* s_bf  = (float*)(smraw + 7168);
    float* s_ba1 = (float*)(smraw + 7680);
    float* s_wa2 = (float*)(smraw + 7936);
    float* s_hid = (float*)(smraw + 8192);   // 64 x 132
    float* s_B   = (float*)(smraw + 41984);  // 128 x 36
    float* s_atth = s_hid;                   // gate scratch 64x68 overlay
    __shared__ int sh_np, sh_t0;

    int tid = threadIdx.x;
    int tile0 = blockIdx.x * 64;
    if (tid < 64) {
        int e = g_perm[tile0 + tid];
        s_src[tid] = edge_index[e];
        s_dst[tid] = edge_index[NE + e];
        s_et[tid]  = edge_type[e];
#pragma unroll
        for (int j = 0; j < D_EF; j++) s_ea[tid * D_EF + j] = edge_attr[e * D_EF + j];
    } else if (tid < 128) {
        s_ba1[tid - 64] = b_att1[l * 64 + (tid - 64)];
    } else if (tid < 192) {
        s_wa2[tid - 128] = W_att2[l * 64 + (tid - 128)];
    }
    __syncthreads();
    if (tid == 0) {
        int t0 = s_et[0];
        sh_t0 = t0;
        sh_np = (s_et[63] == t0) ? 1 : 2;
    }
    __syncthreads();
    int npasses = sh_np;
    float ba2 = b_att2[l];
    int wid = tid >> 5, lane = tid & 31;
    int wy = wid >> 2, wx = wid & 3;
    int g = lane >> 2, tig = lane & 3;

    for (int p = 0; p < npasses; p++) {
        int t = (npasses == 1) ? sh_t0 : p;
        for (int idx = tid; idx < D_EF * D_H; idx += 256) s_Wf[idx] = g_Wf[l][t][idx];
        if (tid < D_H) s_bf[tid] = g_bf[l][t][tid];
        // attention gate (uses s_hid as scratch)
        if (t == 1) {
            for (int idx = tid; idx < 64 * 64; idx += 256) {
                int i = idx >> 6, m = idx & 63;
                int d = s_dst[i], s = s_src[i];
                float v = __ldg(g_P + (size_t)d * PC + 512 + m) +
                          __ldg(g_P + (size_t)s * PC + 576 + m) + s_ba1[m];
                s_atth[m * 68 + i] = fmaxf(v, 0.f);
            }
            __syncthreads();
            if (tid < 64) {
                float z = ba2;
#pragma unroll 8
                for (int m = 0; m < 64; m++) z = fmaf(s_atth[m * 68 + tid], s_wa2[m], z);
                s_att[tid] = 1.f / (1.f + expf(-z));
            }
        }
        __syncthreads();
        // phase1: hidden = relu(P_dst + P_src + ea@Wf + bf)
        {
            int q = tid & 31, gi = tid >> 5;
            int k4 = q * 4;
            int cD = t ? 256 : 0;
            float4 bf4 = *(const float4*)(s_bf + k4);
#pragma unroll 2
            for (int i = gi; i < 64; i += 8) {
                int d = s_dst[i], s = s_src[i];
                float4 vd = __ldg((const float4*)(g_P + (size_t)d * PC + cD + k4));
                float4 vs = __ldg((const float4*)(g_P + (size_t)s * PC + cD + 128 + k4));
                float a0 = bf4.x + vd.x + vs.x;
                float a1 = bf4.y + vd.y + vs.y;
                float a2v = bf4.z + vd.z + vs.z;
                float a3 = bf4.w + vd.w + vs.w;
#pragma unroll
                for (int j = 0; j < D_EF; j++) {
                    float e = s_ea[i * D_EF + j];
                    float4 w = *(const float4*)(s_Wf + j * D_H + k4);
                    a0 = fmaf(e, w.x, a0); a1 = fmaf(e, w.y, a1);
                    a2v = fmaf(e, w.z, a2v); a3 = fmaf(e, w.w, a3);
                }
                float* hp = s_hid + i * 132 + k4;
                *(float2*)hp = make_float2(f2tf32(fmaxf(a0, 0.f)), f2tf32(fmaxf(a1, 0.f)));
                *(float2*)(hp + 2) = make_float2(f2tf32(fmaxf(a2v, 0.f)), f2tf32(fmaxf(a3, 0.f)));
            }
        }
        // GEMM2: 64x128x128 via tf32 mma, 32-K B chunks
        const float* W2T = g_W2T[l][t];
        const float* b2 = (t ? b_eav2 : b_leg2) + l * D_H;
        float c[2][4][4];
#pragma unroll
        for (int mt = 0; mt < 2; mt++)
#pragma unroll
            for (int nt = 0; nt < 4; nt++)
#pragma unroll
                for (int j = 0; j < 4; j++) c[mt][nt][j] = 0.f;
        for (int chunk = 0; chunk < 4; chunk++) {
            __syncthreads();
            for (int idx = tid; idx < 128 * 8; idx += 256) {
                int n = idx >> 3, q4 = (idx & 7) * 4;
                float4 v = *(const float4*)(W2T + n * 128 + chunk * 32 + q4);
                v.x = f2tf32(v.x); v.y = f2tf32(v.y); v.z = f2tf32(v.z); v.w = f2tf32(v.w);
                *(float4*)(s_B + n * 36 + q4) = v;
            }
            __syncthreads();
#pragma unroll
            for (int ks = 0; ks < 4; ks++) {
                int kh = chunk * 32 + ks * 8 + tig;  // col in s_hid
                int kb = ks * 8 + tig;               // col in s_B chunk
                uint32_t a[2][4];
#pragma unroll
                for (int mt = 0; mt < 2; mt++) {
                    int base = wy * 32 + mt * 16;
                    a[mt][0] = __float_as_uint(s_hid[(base + g) * 132 + kh]);
                    a[mt][1] = __float_as_uint(s_hid[(base + g + 8) * 132 + kh]);
                    a[mt][2] = __float_as_uint(s_hid[(base + g) * 132 + kh + 4]);
                    a[mt][3] = __float_as_uint(s_hid[(base + g + 8) * 132 + kh + 4]);
                }
#pragma unroll
                for (int nt = 0; nt < 4; nt++) {
                    int nb = wx * 32 + nt * 8 + g;
                    uint32_t b0 = __float_as_uint(s_B[nb * 36 + kb]);
                    uint32_t b1 = __float_as_uint(s_B[nb * 36 + kb + 4]);
                    mma8(c[0][nt], a[0], b0, b1);
                    mma8(c[1][nt], a[1], b0, b1);
                }
            }
        }
        // epilogue: bias + gate + scatter
#pragma unroll
        for (int mt = 0; mt < 2; mt++) {
            int i0 = wy * 32 + mt * 16 + g;
            int i1 = i0 + 8;
            bool p0 = (npasses == 1) || (s_et[i0] == t);
            bool p1 = (npasses == 1) || (s_et[i1] == t);
            float sc0 = t ? s_att[i0] : 1.f;
            float sc1 = t ? s_att[i1] : 1.f;
            int d0 = s_dst[i0], d1 = s_dst[i1];
#pragma unroll
            for (int nt = 0; nt < 4; nt++) {
                int col = wx * 32 + nt * 8 + 2 * tig;
                float2 bv = *(const float2*)(b2 + col);
                if (p0) red2(g_aggr + (size_t)d0 * D_H + col,
                             (c[mt][nt][0] + bv.x) * sc0, (c[mt][nt][1] + bv.y) * sc0);
                if (p1) red2(g_aggr + (size_t)d1 * D_H + col,
                             (c[mt][nt][2] + bv.x) * sc1, (c[mt][nt][3] + bv.y) * sc1);
            }
        }
        __syncthreads();
    }
}

// ------------------------- k_update_mma: mma + LN + residual -----------------
// smem (floats): sA 64x68 | sB 128x68 | bias 128 | gam 128 | bet 128 |
// P1 64x4 | P2 64x4 | mu 64 | rs 64
#define SMEM_UPD ((64 * 68 + 128 * 68 + 128 * 3 + 64 * 4 * 2 + 128) * 4)
__global__ void __launch_bounds__(256, 4) k_update_mma(
    int l, const float* __restrict__ b_upd,
    const float* __restrict__ ln_g, const float* __restrict__ ln_b) {
    extern __shared__ __align__(16) float sm[];
    float* sA = sm;                       // 64 x 68
    float* sB = sA + 64 * 68;             // 128 x 68
    float* sBias = sB + 128 * 68;         // 128
    float* sGam = sBias + 128;            // 128
    float* sBet = sGam + 128;             // 128
    float* sP1 = sBet + 128;              // 64 x 4
    float* sP2 = sP1 + 256;               // 64 x 4
    float* sMu = sP2 + 256;               // 64
    float* sRs = sMu + 64;                // 64
    int tid = threadIdx.x;
    int row0 = blockIdx.x * 64;
    int wid = tid >> 5, lane = tid & 31;
    int wy = wid >> 2, wx = wid & 3;
    int g = lane >> 2, tig = lane & 3;
    if (tid < 128) {
        sBias[tid] = b_upd[l * D_H + tid];
        sGam[tid] = ln_g[l * D_H + tid];
        sBet[tid] = ln_b[l * D_H + tid];
    }
    const float* WuT = g_WuT[l];
    float c[2][4][4];
#pragma unroll
    for (int mt = 0; mt < 2; mt++)
#pragma unroll
        for (int nt = 0; nt < 4; nt++)
#pragma unroll
            for (int j = 0; j < 4; j++) c[mt][nt][j] = 0.f;
    for (int chunk = 0; chunk < 4; chunk++) {
        __syncthreads();
        const float* Asrc = (chunk < 2) ? g_x : g_aggr;
        int cbase = (chunk & 1) * 64;
        for (int idx = tid; idx < 64 * 16; idx += 256) {
            int m = idx >> 4, q4 = (idx & 15) * 4;
            int r = row0 + m;
            float4 v = make_float4(0.f, 0.f, 0.f, 0.f);
            if (r < NN) v = *(const float4*)(Asrc + r * D_H + cbase + q4);
            v.x = f2tf32(v.x); v.y = f2tf32(v.y); v.z = f2tf32(v.z); v.w = f2tf32(v.w);
            *(float4*)(sA + m * 68 + q4) = v;
        }
        for (int idx = tid; idx < 128 * 16; idx += 256) {
            int n = idx >> 4, q4 = (idx & 15) * 4;
            float4 v = *(const float4*)(WuT + n * 256 + chunk * 64 + q4);
            v.x = f2tf32(v.x); v.y = f2tf32(v.y); v.z = f2tf32(v.z); v.w = f2tf32(v.w);
            *(float4*)(sB + n * 68 + q4) = v;
        }
        __syncthreads();
#pragma unroll
        for (int ks = 0; ks < 8; ks++) {
            int ka = ks * 8 + tig;
            uint32_t a[2][4];
#pragma unroll
            for (int mt = 0; mt < 2; mt++) {
                int base = wy * 32 + mt * 16;
                a[mt][0] = __float_as_uint(sA[(base + g) * 68 + ka]);
                a[mt][1] = __float_as_uint(sA[(base + g + 8) * 68 + ka]);
                a[mt][2] = __float_as_uint(sA[(base + g) * 68 + ka + 4]);
                a[mt][3] = __float_as_uint(sA[(base + g + 8) * 68 + ka + 4]);
            }
#pragma unroll
            for (int nt = 0; nt < 4; nt++) {
                int nb = wx * 32 + nt * 8 + g;
                uint32_t b0 = __float_as_uint(sB[nb * 68 + ka]);
                uint32_t b1 = __float_as_uint(sB[nb * 68 + ka + 4]);
                mma8(c[0][nt], a[0], b0, b1);
                mma8(c[1][nt], a[1], b0, b1);
            }
        }
    }
    // add bias, accumulate per-row partial sums
#pragma unroll
    for (int mt = 0; mt < 2; mt++) {
        float s1a = 0.f, s2a = 0.f, s1b = 0.f, s2b = 0.f;
#pragma unroll
        for (int nt = 0; nt < 4; nt++) {
            int col = wx * 32 + nt * 8 + 2 * tig;
            float b0 = sBias[col], b1 = sBias[col + 1];
            c[mt][nt][0] += b0; c[mt][nt][1] += b1;
            c[mt][nt][2] += b0; c[mt][nt][3] += b1;
            s1a += c[mt][nt][0] + c[mt][nt][1];
            s2a += c[mt][nt][0] * c[mt][nt][0] + c[mt][nt][1] * c[mt][nt][1];
            s1b += c[mt][nt][2] + c[mt][nt][3];
            s2b += c[mt][nt][2] * c[mt][nt][2] + c[mt][nt][3] * c[mt][nt][3];
        }
#pragma unroll
        for (int d = 1; d <= 2; d <<= 1) {
            s1a += __shfl_xor_sync(0xffffffff, s1a, d);
            s2a += __shfl_xor_sync(0xffffffff, s2a, d);
            s1b += __shfl_xor_sync(0xffffffff, s1b, d);
            s2b += __shfl_xor_sync(0xffffffff, s2b, d);
        }
        if (tig == 0) {
            int ra = wy * 32 + mt * 16 + g;
            sP1[ra * 4 + wx] = s1a;
            sP2[ra * 4 + wx] = s2a;
            sP1[(ra + 8) * 4 + wx] = s1b;
            sP2[(ra + 8) * 4 + wx] = s2b;
        }
    }
    __syncthreads();
    if (tid < 64) {
        float s1 = sP1[tid * 4] + sP1[tid * 4 + 1] + sP1[tid * 4 + 2] + sP1[tid * 4 + 3];
        float s2 = sP2[tid * 4] + sP2[tid * 4 + 1] + sP2[tid * 4 + 2] + sP2[tid * 4 + 3];
        float mu = s1 * (1.f / D_H);
        float var = fmaxf(s2 * (1.f / D_H) - mu * mu, 0.f);
        sMu[tid] = mu;
        sRs[tid] = rsqrtf(var + LN_EPS);
    }
    __syncthreads();
#pragma unroll
    for (int mt = 0; mt < 2; mt++) {
        int ra = wy * 32 + mt * 16 + g;
        int rows[2] = {ra, ra + 8};
#pragma unroll
        for (int h = 0; h < 2; h++) {
            int rr = rows[h];
            int grow = row0 + rr;
            if (grow >= NN) continue;
            float mu = sMu[rr], rs = sRs[rr];
#pragma unroll
            for (int nt = 0; nt < 4; nt++) {
                int col = wx * 32 + nt * 8 + 2 * tig;
                float v0 = c[mt][nt][h * 2], v1 = c[mt][nt][h * 2 + 1];
                float2 xo = *(const float2*)(g_x + (size_t)grow * D_H + col);
                float h0 = (v0 - mu) * rs * sGam[col] + sBet[col];
                float h1 = (v1 - mu) * rs * sGam[col + 1] + sBet[col + 1];
                float o0 = fmaxf(fmaxf(h0, 0.f) + xo.x, 0.f);
                float o1 = fmaxf(fmaxf(h1, 0.f) + xo.y, 0.f);
                *(float2*)(g_x + (size_t)grow * D_H + col) = make_float2(o0, o1);
            }
        }
    }
}

// ------------------------- k_pool -------------------------------------------
__global__ void k_pool() {
    __shared__ float sp[256];
    int tid = threadIdx.x;
    int row0 = blockIdx.x * 64;
    int k = tid & 127, ih = tid >> 7;
    float v = 0.f;
    for (int i = ih; i < 64; i += 2) {
        int r = row0 + i;
        if (r < NN) v += g_x[r * D_H + k];
    }
    sp[tid] = v;
    __syncthreads();
    if (tid < 128) atomicAdd(&g_pool[k], sp[tid] + sp[tid + 128]);
}

// ------------------------- k_head -------------------------------------------
__global__ void k_head(float* out, const float* __restrict__ traj,
                       const float* __restrict__ W_ref1, const float* __restrict__ b_ref1,
                       const float* __restrict__ W_ref2, const float* __restrict__ b_ref2) {
    __shared__ float sg[D_H], sr1[D_H];
    int tid = threadIdx.x; // 128
    sg[tid] = g_pool[tid] * (1.f / NN);
    __syncthreads();
    float acc = b_ref1[tid];
    for (int c = 0; c < D_H; c++) acc = fmaf(sg[c], W_ref1[c * D_H + tid], acc);
    sr1[tid] = fmaxf(acc, 0.f);
    __syncthreads();
    if (tid < D_OUT) {
        float r2 = b_ref2[tid];
        for (int c = 0; c < D_H; c++) r2 = fmaf(sr1[c], W_ref2[c * D_OUT + tid], r2);
        if (tid < 3) out[164 + tid] = traj[tid] + r2;
    }
    out[167 + tid] = sg[tid];
}

// ------------------------- launch ------------------------------------------
extern "C" void kernel_launch(void* const* d_in, const int* in_sizes, int n_in,
                              void* d_out, int out_size) {
    const float* x_in      = (const float*)d_in[0];
    const float* edge_attr = (const float*)d_in[1];
    const int*   edge_index= (const int*)d_in[2];
    const int*   edge_type = (const int*)d_in[3];
    const float* beam      = (const float*)d_in[5];
    const float* ris       = (const float*)d_in[6];
    const float* traj      = (const float*)d_in[7];
    const float* W_node = (const float*)d_in[8];
    const float* b_node = (const float*)d_in[9];
    const float* W_edge = (const float*)d_in[10];
    const float* b_edge = (const float*)d_in[11];
    const float* W_leg1 = (const float*)d_in[12];
    const float* b_leg1 = (const float*)d_in[13];
    const float* W_leg2 = (const float*)d_in[14];
    const float* b_leg2 = (const float*)d_in[15];
    const float* W_eav1 = (const float*)d_in[16];
    const float* b_eav1 = (const float*)d_in[17];
    const float* W_eav2 = (const float*)d_in[18];
    const float* b_eav2 = (const float*)d_in[19];
    const float* W_att1 = (const float*)d_in[20];
    const float* b_att1 = (const float*)d_in[21];
    const float* W_att2 = (const float*)d_in[22];
    const float* b_att2 = (const float*)d_in[23];
    const float* W_upd  = (const float*)d_in[24];
    const float* b_upd  = (const float*)d_in[25];
    const float* ln_g   = (const float*)d_in[26];
    const float* ln_b   = (const float*)d_in[27];
    const float* W_ref1 = (const float*)d_in[28];
    const float* b_ref1 = (const float*)d_in[29];
    const float* W_ref2 = (const float*)d_in[30];
    const float* b_ref2 = (const float*)d_in[31];
    float* out = (float*)d_out;

    cudaFuncSetAttribute(k_proj_mma,   cudaFuncAttributeMaxDynamicSharedMemorySize, SMEM_PROJ);
    cudaFuncSetAttribute(k_edge,       cudaFuncAttributeMaxDynamicSharedMemorySize, SMEM_EDGE);
    cudaFuncSetAttribute(k_update_mma, cudaFuncAttributeMaxDynamicSharedMemorySize, SMEM_UPD);

    void* aggr_ptr = nullptr;
    cudaGetSymbolAddress(&aggr_ptr, g_aggr);

    k_setup<<<21, 256>>>(out, beam, ris, W_leg1, b_leg1, W_eav1, b_eav1,
                         W_edge, b_edge, W_att1, W_leg2, W_eav2, W_upd);
    k_partition<<<(NE + 255) / 256, 256>>>(edge_type);
    k_embed<<<NT64, 256>>>(x_in, W_node, b_node);

    for (int l = 0; l < N_L; l++) {
        cudaMemsetAsync(aggr_ptr, 0, (size_t)NN * D_H * sizeof(float));
        k_proj_mma<<<dim3(NT64, 5), 256, SMEM_PROJ>>>(l);
        k_edge<<<NE / 64, 256, SMEM_EDGE>>>(l, edge_index, edge_type, edge_attr,
                                            b_leg2, b_eav2, W_att2, b_att2, b_att1);
        k_update_mma<<<NT64, 256, SMEM_UPD>>>(l, b_upd, ln_g, ln_b);
    }

    k_pool<<<NT64, 256>>>();
    k_head<<<1, 128>>>(out, traj, W_ref1, b_ref1, W_ref2, b_ref2);
}